// round 2
// baseline (speedup 1.0000x reference)
#include <cuda_runtime.h>
#include <math.h>

#define NN 50000
#define NE 400000
#define NEL (NE + NN)
#define DIN 128
#define F 256
#define H 8
#define C 32

// ---------------- scratch (device globals; no allocation) ----------------
__device__ float    g_h [NN * F];      // h = x @ W for current layer
__device__ float    g_x1[NN * F];      // layer-1 output
__device__ float    g_x2[NN * F];      // layer-2 output
__device__ float    g_as[NN * H];
__device__ float    g_ad[NN * H];
__device__ unsigned g_m [NN * H];      // segment max (monotone-encoded)
__device__ float    g_den[NN * H];     // segment sum of exp
__device__ float    g_ex[NEL * H];     // e, then exp(e - m)
__device__ float    g_P [NN * 64];     // [Prow(32) | Pcol(32)] per node

// monotone float<->uint encoding for atomicMax on floats
__device__ __forceinline__ unsigned fenc(float f) {
    unsigned u = __float_as_uint(f);
    return (u & 0x80000000u) ? ~u : (u | 0x80000000u);
}
__device__ __forceinline__ float fdec(unsigned u) {
    return (u & 0x80000000u) ? __uint_as_float(u & 0x7FFFFFFFu)
                             : __uint_as_float(~u);
}

// ---------------- GEMM: C[M,256] = A[M,K] @ B[K,256] ----------------
// 64x64 tile, BK=16, 256 threads, 4x4 per-thread microtile.
__global__ void gemm_kernel(const float* __restrict__ A, const float* __restrict__ B,
                            float* __restrict__ Cp, int M, int K) {
    const int N = 256;
    __shared__ float As[16][68];
    __shared__ float Bs[16][64];
    int tid = threadIdx.x;
    int tx = tid & 15, ty = tid >> 4;
    int rowBase = blockIdx.x * 64;
    int colBase = blockIdx.y * 64;

    float acc[4][4] = {};

    int ar = tid >> 2;            // A-tile row this thread loads
    int ac = (tid & 3) << 2;      // A-tile col (float4)
    int br = tid >> 4;            // B-tile row
    int bc = (tid & 15) << 2;     // B-tile col (float4)

    for (int k0 = 0; k0 < K; k0 += 16) {
        float4 av = make_float4(0.f, 0.f, 0.f, 0.f);
        int gr = rowBase + ar;
        if (gr < M) av = *(const float4*)&A[gr * K + k0 + ac];
        As[ac + 0][ar] = av.x; As[ac + 1][ar] = av.y;
        As[ac + 2][ar] = av.z; As[ac + 3][ar] = av.w;

        float4 bv = *(const float4*)&B[(k0 + br) * N + colBase + bc];
        *(float4*)&Bs[br][bc] = bv;
        __syncthreads();

#pragma unroll
        for (int kk = 0; kk < 16; kk++) {
            float4 a = *(float4*)&As[kk][ty * 4];
            float4 b = *(float4*)&Bs[kk][tx * 4];
            float am[4] = {a.x, a.y, a.z, a.w};
            float bn[4] = {b.x, b.y, b.z, b.w};
#pragma unroll
            for (int m = 0; m < 4; m++)
#pragma unroll
                for (int n = 0; n < 4; n++)
                    acc[m][n] += am[m] * bn[n];
        }
        __syncthreads();
    }

#pragma unroll
    for (int m = 0; m < 4; m++) {
        int gr = rowBase + ty * 4 + m;
        if (gr < M) {
            float4 v = make_float4(acc[m][0], acc[m][1], acc[m][2], acc[m][3]);
            *(float4*)&Cp[gr * N + colBase + tx * 4] = v;
        }
    }
}

// ---------------- alpha_src/alpha_dst: warp per (node, head) ----------------
__global__ void alpha_kernel(const float* __restrict__ a_src, const float* __restrict__ a_dst) {
    int w = (blockIdx.x * blockDim.x + threadIdx.x) >> 5;
    int lane = threadIdx.x & 31;
    if (w >= NN * H) return;
    int n = w >> 3, hh = w & 7;
    float v = g_h[n * F + hh * C + lane];
    float s = v * a_src[hh * C + lane];
    float d = v * a_dst[hh * C + lane];
#pragma unroll
    for (int o = 16; o; o >>= 1) {
        s += __shfl_xor_sync(0xFFFFFFFFu, s, o);
        d += __shfl_xor_sync(0xFFFFFFFFu, d, o);
    }
    if (lane == 0) { g_as[w] = s; g_ad[w] = d; }
}

// ---------------- init: zero agg buffer, reset m/den ----------------
__global__ void init_kernel(float* __restrict__ agg) {
    int i = blockIdx.x * blockDim.x + threadIdx.x;
    if (i < NN * F) agg[i] = 0.f;
    if (i < NN * H) { g_m[i] = 0x007FFFFFu; /* enc(-inf) */ g_den[i] = 0.f; }
}

// ---------------- e = leaky_relu(as[src]+ad[dst]); segment max ----------------
__global__ void e_kernel(const int* __restrict__ ei) {
    int idx = blockIdx.x * blockDim.x + threadIdx.x;
    if (idx >= NEL * H) return;
    int e = idx >> 3, hh = idx & 7;
    int s, d;
    if (e < NE) { s = ei[e]; d = ei[NE + e]; } else { s = d = e - NE; }
    float v = g_as[s * H + hh] + g_ad[d * H + hh];
    v = (v > 0.f) ? v : 0.2f * v;
    g_ex[idx] = v;
    atomicMax(&g_m[d * H + hh], fenc(v));
}

// ---------------- ex = exp(e - m[dst]); segment sum ----------------
__global__ void ex_kernel(const int* __restrict__ ei) {
    int idx = blockIdx.x * blockDim.x + threadIdx.x;
    if (idx >= NEL * H) return;
    int e = idx >> 3, hh = idx & 7;
    int d;
    if (e < NE) d = ei[NE + e]; else d = e - NE;
    float v = g_ex[idx];
    float mm = fdec(g_m[d * H + hh]);
    float ex = expf(v - mm);
    g_ex[idx] = ex;
    atomicAdd(&g_den[d * H + hh], ex);
}

// ---------------- message aggregation: warp per edge ----------------
__global__ void agg_kernel(const int* __restrict__ ei, float* __restrict__ out) {
    int w = (blockIdx.x * blockDim.x + threadIdx.x) >> 5;
    int lane = threadIdx.x & 31;
    if (w >= NEL) return;
    int s, d;
    if (w < NE) { s = ei[w]; d = ei[NE + w]; } else { s = d = w - NE; }
#pragma unroll
    for (int ch = 0; ch < 8; ch++) {
        float coef = g_ex[w * 8 + ch] / g_den[d * 8 + ch];
        int i = ch * 32 + lane;
        atomicAdd(&out[d * F + i], g_h[s * F + i] * coef);
    }
}

// ---------------- bias + relu (in place) ----------------
__global__ void biasrelu_kernel(float* __restrict__ x, const float* __restrict__ b) {
    int i = blockIdx.x * blockDim.x + threadIdx.x;
    if (i >= NN * F) return;
    float v = x[i] + b[i & 255];
    x[i] = v > 0.f ? v : 0.f;
}

// ---------------- P = [x2@Wp1[0:256] | x2@Wp1[256:512]] per node ----------------
__global__ void p_kernel(const float* __restrict__ Wp1) {
    __shared__ float Ws[128 * 64];
    __shared__ float xs[4 * 128];
    int nl = threadIdx.x >> 6;   // 0..3  local node
    int j  = threadIdx.x & 63;   // 0..63 output col
    int n  = blockIdx.x * 4 + nl;
    float acc = 0.f;
    for (int k0 = 0; k0 < 256; k0 += 128) {
        for (int t = threadIdx.x; t < 128 * 64; t += 256) {
            int k = t >> 6, jj = t & 63;
            Ws[t] = (jj < 32) ? Wp1[(k0 + k) * 32 + jj]
                              : Wp1[(256 + k0 + k) * 32 + (jj - 32)];
        }
        for (int t = threadIdx.x; t < 4 * 128; t += 256) {
            int n2 = t >> 7, k = t & 127;
            int gn = blockIdx.x * 4 + n2;
            xs[t] = (gn < NN) ? g_x2[gn * F + k0 + k] : 0.f;
        }
        __syncthreads();
#pragma unroll 8
        for (int k = 0; k < 128; k++)
            acc += xs[nl * 128 + k] * Ws[k * 64 + j];
        __syncthreads();
    }
    if (n < NN) g_P[n * 64 + j] = acc;
}

// ---------------- fused edge head: warp per edge ----------------
__global__ void edge_kernel(const int* __restrict__ ei, const float* __restrict__ ea,
                            const float* __restrict__ Wm1, const float* __restrict__ bm1,
                            const float* __restrict__ Wm2, const float* __restrict__ bm2,
                            const float* __restrict__ Wp1, const float* __restrict__ bp1,
                            const float* __restrict__ Wp2, const float* __restrict__ bp2,
                            float* __restrict__ out) {
    __shared__ float sWm1[1024], sWm2[1024], sWpc[1024];
    __shared__ float sbm1[32], sbm2[32], sbp1[32], sWp2[32];
    for (int t = threadIdx.x; t < 1024; t += blockDim.x) {
        sWm1[t] = Wm1[t];
        sWm2[t] = Wm2[t];
        sWpc[t] = Wp1[512 * 32 + t];
    }
    if (threadIdx.x < 32) {
        sbm1[threadIdx.x] = bm1[threadIdx.x];
        sbm2[threadIdx.x] = bm2[threadIdx.x];
        sbp1[threadIdx.x] = bp1[threadIdx.x];
        sWp2[threadIdx.x] = Wp2[threadIdx.x];
    }
    __syncthreads();

    int w = (blockIdx.x * blockDim.x + threadIdx.x) >> 5;
    int lane = threadIdx.x & 31;
    if (w >= NE) return;

    float eav = ea[w * 32 + lane];

    float a1 = sbm1[lane];
#pragma unroll
    for (int k = 0; k < 32; k++)
        a1 += __shfl_sync(0xFFFFFFFFu, eav, k) * sWm1[k * 32 + lane];
    a1 = fmaxf(a1, 0.f);

    float a2 = sbm2[lane];
#pragma unroll
    for (int k = 0; k < 32; k++)
        a2 += __shfl_sync(0xFFFFFFFFu, a1, k) * sWm2[k * 32 + lane];
    a2 = fmaxf(a2, 0.f);

    float q = 0.f;
#pragma unroll
    for (int k = 0; k < 32; k++)
        q += __shfl_sync(0xFFFFFFFFu, a2, k) * sWpc[k * 32 + lane];

    int r = ei[w], c = ei[NE + w];
    float t = g_P[r * 64 + lane] + g_P[c * 64 + 32 + lane] + q + sbp1[lane];
    t = fmaxf(t, 0.f);

    float s = t * sWp2[lane];
#pragma unroll
    for (int o = 16; o; o >>= 1) s += __shfl_xor_sync(0xFFFFFFFFu, s, o);
    if (lane == 0) out[w] = s + bp2[0];
}

// ---------------- host driver ----------------
static void run_gat_layer(const float* xin, int K, const float* W,
                          const float* a_s, const float* a_d, const float* b,
                          const int* ei, float* h_ptr, float* out_ptr) {
    dim3 ggrid((NN + 63) / 64, 4);
    gemm_kernel<<<ggrid, 256>>>(xin, W, h_ptr, NN, K);
    alpha_kernel<<<(NN * H * 32 + 255) / 256, 256>>>(a_s, a_d);
    init_kernel<<<(NN * F + 255) / 256, 256>>>(out_ptr);
    e_kernel<<<(NEL * H + 255) / 256, 256>>>(ei);
    ex_kernel<<<(NEL * H + 255) / 256, 256>>>(ei);
    agg_kernel<<<(NEL + 7) / 8, 256>>>(ei, out_ptr);
    biasrelu_kernel<<<(NN * F + 255) / 256, 256>>>(out_ptr, b);
}

extern "C" void kernel_launch(void* const* d_in, const int* in_sizes, int n_in,
                              void* d_out, int out_size) {
    const float* x      = (const float*)d_in[0];
    const int*   ei     = (const int*)  d_in[1];
    const float* ea     = (const float*)d_in[2];
    const float* W1     = (const float*)d_in[3];
    const float* a_src1 = (const float*)d_in[4];
    const float* a_dst1 = (const float*)d_in[5];
    const float* b1     = (const float*)d_in[6];
    const float* W2     = (const float*)d_in[7];
    const float* a_src2 = (const float*)d_in[8];
    const float* a_dst2 = (const float*)d_in[9];
    const float* b2     = (const float*)d_in[10];
    const float* Wm1    = (const float*)d_in[11];
    const float* bm1    = (const float*)d_in[12];
    const float* Wm2    = (const float*)d_in[13];
    const float* bm2    = (const float*)d_in[14];
    const float* Wp1    = (const float*)d_in[15];
    const float* bp1    = (const float*)d_in[16];
    const float* Wp2    = (const float*)d_in[17];
    const float* bp2    = (const float*)d_in[18];
    float* out = (float*)d_out;

    float *gh, *gx1, *gx2;
    cudaGetSymbolAddress((void**)&gh,  g_h);
    cudaGetSymbolAddress((void**)&gx1, g_x1);
    cudaGetSymbolAddress((void**)&gx2, g_x2);

    run_gat_layer(x,   DIN, W1, a_src1, a_dst1, b1, ei, gh, gx1);
    run_gat_layer(gx1, F,   W2, a_src2, a_dst2, b2, ei, gh, gx2);

    p_kernel<<<(NN + 3) / 4, 256>>>(Wp1);
    edge_kernel<<<(NE + 7) / 8, 256>>>(ei, ea, Wm1, bm1, Wm2, bm2,
                                       Wp1, bp1, Wp2, bp2, out);
}

// round 5
// speedup vs baseline: 1.2129x; 1.2129x over previous
#include <cuda_runtime.h>
#include <math.h>

#define NN 50000
#define NE 400000
#define NEL (NE + NN)
#define DIN 128
#define F 256
#define H 8
#define C 32

// ---------------- scratch (device globals; no allocation) ----------------
__device__ float    g_h [NN * F];      // h = x @ W for current layer
__device__ float    g_x1[NN * F];      // layer-1 output
__device__ float    g_x2[NN * F];      // layer-2 output
__device__ float    g_as[NN * H];
__device__ float    g_ad[NN * H];
__device__ unsigned g_m [NN * H];      // segment max (monotone-encoded)
__device__ float    g_den[NN * H];     // segment sum of exp
__device__ float    g_ex[NEL * H];     // e, then exp(e - m)
__device__ float    g_P [NN * 64];     // [Prow(32) | Pcol(32)] per node
__device__ float    g_Wcat[256 * 64];  // repacked Wp1[0:512] as [256][64]

// monotone float<->uint encoding for atomicMax on floats
__device__ __forceinline__ unsigned fenc(float f) {
    unsigned u = __float_as_uint(f);
    return (u & 0x80000000u) ? ~u : (u | 0x80000000u);
}
__device__ __forceinline__ float fdec(unsigned u) {
    return (u & 0x80000000u) ? __uint_as_float(u & 0x7FFFFFFFu)
                             : __uint_as_float(~u);
}

// ---------------- tf32 split helpers ----------------
__device__ __forceinline__ void split_tf32(float v, unsigned& hi, unsigned& lo) {
    unsigned h;
    asm("cvt.rna.tf32.f32 %0, %1;" : "=r"(h) : "f"(v));
    float r = v - __uint_as_float(h);
    unsigned l;
    asm("cvt.rna.tf32.f32 %0, %1;" : "=r"(l) : "f"(r));
    hi = h; lo = l;
}

__device__ __forceinline__ void mma_tf32(float* d, const unsigned* a, const unsigned* b) {
    asm volatile(
        "mma.sync.aligned.m16n8k8.row.col.f32.tf32.tf32.f32 "
        "{%0,%1,%2,%3}, {%4,%5,%6,%7}, {%8,%9}, {%0,%1,%2,%3};\n"
        : "+f"(d[0]), "+f"(d[1]), "+f"(d[2]), "+f"(d[3])
        : "r"(a[0]), "r"(a[1]), "r"(a[2]), "r"(a[3]), "r"(b[0]), "r"(b[1]));
}

// ---------------- tensor-core GEMM: C[M,N] = A[M,K] @ B[K,N] ----------------
// Block tile 128x64, 8 warps (4m x 2n), warp tile 32x32 (2x4 m16n8 atoms),
// BK=16, split-TF32 (3 mma per fragment pair) for fp32-level accuracy.
// Requires: K % 16 == 0, N % 64 == 0.
__global__ void gemm_tc(const float* __restrict__ A, const float* __restrict__ B,
                        float* __restrict__ Cp, int M, int N, int K) {
    __shared__ float As[128 * 20];   // [row][k], stride 20 (conflict-free frags)
    __shared__ float Bs[16 * 72];    // [k][n], stride 72 (conflict-free frags)

    int tid = threadIdx.x;
    int lane = tid & 31, wid = tid >> 5;
    int wm = wid & 3, wn = wid >> 2;      // 4 m-warps x 2 n-warps
    int g = lane >> 2, tg = lane & 3;
    int rowBase = blockIdx.x * 128;
    int colBase = blockIdx.y * 64;

    float acc[2][4][4];
#pragma unroll
    for (int i = 0; i < 2; i++)
#pragma unroll
        for (int j = 0; j < 4; j++)
#pragma unroll
            for (int q = 0; q < 4; q++) acc[i][j][q] = 0.f;

    for (int k0 = 0; k0 < K; k0 += 16) {
        // load A tile 128x16 (two float4 per thread)
#pragma unroll
        for (int l = 0; l < 2; l++) {
            int idx = tid + l * 256;
            int row = idx >> 2, c4 = (idx & 3) << 2;
            float4 v = make_float4(0.f, 0.f, 0.f, 0.f);
            if (rowBase + row < M)
                v = *(const float4*)&A[(size_t)(rowBase + row) * K + k0 + c4];
            *(float4*)&As[row * 20 + c4] = v;
        }
        // load B tile 16x64 (one float4 per thread)
        {
            int row = tid >> 4, c4 = (tid & 15) << 2;
            float4 v = *(const float4*)&B[(size_t)(k0 + row) * N + colBase + c4];
            *(float4*)&Bs[row * 72 + c4] = v;
        }
        __syncthreads();

#pragma unroll
        for (int k8 = 0; k8 < 16; k8 += 8) {
            unsigned ahi[2][4], alo[2][4], bhi[4][2], blo[4][2];
#pragma unroll
            for (int i = 0; i < 2; i++) {
                int r0 = wm * 32 + i * 16 + g;
                float v0 = As[r0 * 20 + k8 + tg];
                float v1 = As[(r0 + 8) * 20 + k8 + tg];
                float v2 = As[r0 * 20 + k8 + tg + 4];
                float v3 = As[(r0 + 8) * 20 + k8 + tg + 4];
                split_tf32(v0, ahi[i][0], alo[i][0]);
                split_tf32(v1, ahi[i][1], alo[i][1]);
                split_tf32(v2, ahi[i][2], alo[i][2]);
                split_tf32(v3, ahi[i][3], alo[i][3]);
            }
#pragma unroll
            for (int j = 0; j < 4; j++) {
                int c0 = wn * 32 + j * 8 + g;
                float v0 = Bs[(k8 + tg) * 72 + c0];
                float v1 = Bs[(k8 + tg + 4) * 72 + c0];
                split_tf32(v0, bhi[j][0], blo[j][0]);
                split_tf32(v1, bhi[j][1], blo[j][1]);
            }
#pragma unroll
            for (int i = 0; i < 2; i++)
#pragma unroll
                for (int j = 0; j < 4; j++) {
                    mma_tf32(acc[i][j], alo[i], bhi[j]);   // lo*hi
                    mma_tf32(acc[i][j], ahi[i], blo[j]);   // hi*lo
                    mma_tf32(acc[i][j], ahi[i], bhi[j]);   // hi*hi
                }
        }
        __syncthreads();
    }

    // epilogue
#pragma unroll
    for (int i = 0; i < 2; i++) {
        int r = rowBase + wm * 32 + i * 16 + g;
#pragma unroll
        for (int j = 0; j < 4; j++) {
            int c = colBase + wn * 32 + j * 8 + 2 * tg;
            if (r < M) {
                float2 v0 = make_float2(acc[i][j][0], acc[i][j][1]);
                *(float2*)&Cp[(size_t)r * N + c] = v0;
            }
            if (r + 8 < M) {
                float2 v1 = make_float2(acc[i][j][2], acc[i][j][3]);
                *(float2*)&Cp[(size_t)(r + 8) * N + c] = v1;
            }
        }
    }
}

// ---------------- repack Wp1[0:512,0:32] -> g_Wcat[256][64] ----------------
__global__ void repack_kernel(const float* __restrict__ Wp1) {
    int t = blockIdx.x * blockDim.x + threadIdx.x;
    if (t >= 256 * 64) return;
    int k = t >> 6, j = t & 63;
    g_Wcat[t] = (j < 32) ? Wp1[k * 32 + j] : Wp1[(256 + k) * 32 + (j - 32)];
}

// ---------------- alpha_src/alpha_dst: warp per (node, head) ----------------
__global__ void alpha_kernel(const float* __restrict__ a_src, const float* __restrict__ a_dst) {
    int w = (blockIdx.x * blockDim.x + threadIdx.x) >> 5;
    int lane = threadIdx.x & 31;
    if (w >= NN * H) return;
    int n = w >> 3, hh = w & 7;
    float v = g_h[n * F + hh * C + lane];
    float s = v * a_src[hh * C + lane];
    float d = v * a_dst[hh * C + lane];
#pragma unroll
    for (int o = 16; o; o >>= 1) {
        s += __shfl_xor_sync(0xFFFFFFFFu, s, o);
        d += __shfl_xor_sync(0xFFFFFFFFu, d, o);
    }
    if (lane == 0) { g_as[w] = s; g_ad[w] = d; }
}

// ---------------- init: zero agg buffer, reset m/den ----------------
__global__ void init_kernel(float* __restrict__ agg) {
    int i = blockIdx.x * blockDim.x + threadIdx.x;
    if (i < NN * F) agg[i] = 0.f;
    if (i < NN * H) { g_m[i] = 0x007FFFFFu; /* enc(-inf) */ g_den[i] = 0.f; }
}

// ---------------- e = leaky_relu(as[src]+ad[dst]); segment max ----------------
__global__ void e_kernel(const int* __restrict__ ei) {
    int idx = blockIdx.x * blockDim.x + threadIdx.x;
    if (idx >= NEL * H) return;
    int e = idx >> 3, hh = idx & 7;
    int s, d;
    if (e < NE) { s = ei[e]; d = ei[NE + e]; } else { s = d = e - NE; }
    float v = g_as[s * H + hh] + g_ad[d * H + hh];
    v = (v > 0.f) ? v : 0.2f * v;
    g_ex[idx] = v;
    atomicMax(&g_m[d * H + hh], fenc(v));
}

// ---------------- ex = exp(e - m[dst]); segment sum ----------------
__global__ void ex_kernel(const int* __restrict__ ei) {
    int idx = blockIdx.x * blockDim.x + threadIdx.x;
    if (idx >= NEL * H) return;
    int e = idx >> 3, hh = idx & 7;
    int d;
    if (e < NE) d = ei[NE + e]; else d = e - NE;
    float v = g_ex[idx];
    float mm = fdec(g_m[d * H + hh]);
    float ex = expf(v - mm);
    g_ex[idx] = ex;
    atomicAdd(&g_den[d * H + hh], ex);
}

// ---------------- message aggregation: warp per edge ----------------
__global__ void agg_kernel(const int* __restrict__ ei, float* __restrict__ out) {
    int w = (blockIdx.x * blockDim.x + threadIdx.x) >> 5;
    int lane = threadIdx.x & 31;
    if (w >= NEL) return;
    int s, d;
    if (w < NE) { s = ei[w]; d = ei[NE + w]; } else { s = d = w - NE; }
#pragma unroll
    for (int ch = 0; ch < 8; ch++) {
        float coef = g_ex[w * 8 + ch] / g_den[d * 8 + ch];
        int i = ch * 32 + lane;
        atomicAdd(&out[d * F + i], g_h[s * F + i] * coef);
    }
}

// ---------------- bias + relu (in place) ----------------
__global__ void biasrelu_kernel(float* __restrict__ x, const float* __restrict__ b) {
    int i = blockIdx.x * blockDim.x + threadIdx.x;
    if (i >= NN * F) return;
    float v = x[i] + b[i & 255];
    x[i] = v > 0.f ? v : 0.f;
}

// ---------------- fused edge head: warp per edge ----------------
__global__ void edge_kernel(const int* __restrict__ ei, const float* __restrict__ ea,
                            const float* __restrict__ Wm1, const float* __restrict__ bm1,
                            const float* __restrict__ Wm2, const float* __restrict__ bm2,
                            const float* __restrict__ Wp1, const float* __restrict__ bp1,
                            const float* __restrict__ Wp2, const float* __restrict__ bp2,
                            float* __restrict__ out) {
    __shared__ float sWm1[1024], sWm2[1024], sWpc[1024];
    __shared__ float sbm1[32], sbm2[32], sbp1[32], sWp2[32];
    for (int t = threadIdx.x; t < 1024; t += blockDim.x) {
        sWm1[t] = Wm1[t];
        sWm2[t] = Wm2[t];
        sWpc[t] = Wp1[512 * 32 + t];
    }
    if (threadIdx.x < 32) {
        sbm1[threadIdx.x] = bm1[threadIdx.x];
        sbm2[threadIdx.x] = bm2[threadIdx.x];
        sbp1[threadIdx.x] = bp1[threadIdx.x];
        sWp2[threadIdx.x] = Wp2[threadIdx.x];
    }
    __syncthreads();

    int w = (blockIdx.x * blockDim.x + threadIdx.x) >> 5;
    int lane = threadIdx.x & 31;
    if (w >= NE) return;

    float eav = ea[w * 32 + lane];

    float a1 = sbm1[lane];
#pragma unroll
    for (int k = 0; k < 32; k++)
        a1 += __shfl_sync(0xFFFFFFFFu, eav, k) * sWm1[k * 32 + lane];
    a1 = fmaxf(a1, 0.f);

    float a2 = sbm2[lane];
#pragma unroll
    for (int k = 0; k < 32; k++)
        a2 += __shfl_sync(0xFFFFFFFFu, a1, k) * sWm2[k * 32 + lane];
    a2 = fmaxf(a2, 0.f);

    float q = 0.f;
#pragma unroll
    for (int k = 0; k < 32; k++)
        q += __shfl_sync(0xFFFFFFFFu, a2, k) * sWpc[k * 32 + lane];

    int r = ei[w], c = ei[NE + w];
    float t = g_P[r * 64 + lane] + g_P[c * 64 + 32 + lane] + q + sbp1[lane];
    t = fmaxf(t, 0.f);

    float s = t * sWp2[lane];
#pragma unroll
    for (int o = 16; o; o >>= 1) s += __shfl_xor_sync(0xFFFFFFFFu, s, o);
    if (lane == 0) out[w] = s + bp2[0];
}

// ---------------- host driver ----------------
static void run_gat_layer(const float* xin, int K, const float* W,
                          const float* a_s, const float* a_d, const float* b,
                          const int* ei, float* h_ptr, float* out_ptr) {
    dim3 ggrid((NN + 127) / 128, 4);
    gemm_tc<<<ggrid, 256>>>(xin, W, h_ptr, NN, 256, K);
    alpha_kernel<<<(NN * H * 32 + 255) / 256, 256>>>(a_s, a_d);
    init_kernel<<<(NN * F + 255) / 256, 256>>>(out_ptr);
    e_kernel<<<(NEL * H + 255) / 256, 256>>>(ei);
    ex_kernel<<<(NEL * H + 255) / 256, 256>>>(ei);
    agg_kernel<<<(NEL + 7) / 8, 256>>>(ei, out_ptr);
    biasrelu_kernel<<<(NN * F + 255) / 256, 256>>>(out_ptr, b);
}

extern "C" void kernel_launch(void* const* d_in, const int* in_sizes, int n_in,
                              void* d_out, int out_size) {
    const float* x      = (const float*)d_in[0];
    const int*   ei     = (const int*)  d_in[1];
    const float* ea     = (const float*)d_in[2];
    const float* W1     = (const float*)d_in[3];
    const float* a_src1 = (const float*)d_in[4];
    const float* a_dst1 = (const float*)d_in[5];
    const float* b1     = (const float*)d_in[6];
    const float* W2     = (const float*)d_in[7];
    const float* a_src2 = (const float*)d_in[8];
    const float* a_dst2 = (const float*)d_in[9];
    const float* b2     = (const float*)d_in[10];
    const float* Wm1    = (const float*)d_in[11];
    const float* bm1    = (const float*)d_in[12];
    const float* Wm2    = (const float*)d_in[13];
    const float* bm2    = (const float*)d_in[14];
    const float* Wp1    = (const float*)d_in[15];
    const float* bp1    = (const float*)d_in[16];
    const float* Wp2    = (const float*)d_in[17];
    const float* bp2    = (const float*)d_in[18];
    float* out = (float*)d_out;

    float *gh, *gx1, *gx2, *gP, *gW;
    cudaGetSymbolAddress((void**)&gh,  g_h);
    cudaGetSymbolAddress((void**)&gx1, g_x1);
    cudaGetSymbolAddress((void**)&gx2, g_x2);
    cudaGetSymbolAddress((void**)&gP,  g_P);
    cudaGetSymbolAddress((void**)&gW,  g_Wcat);

    run_gat_layer(x,   DIN, W1, a_src1, a_dst1, b1, ei, gh, gx1);
    run_gat_layer(gx1, F,   W2, a_src2, a_dst2, b2, ei, gh, gx2);

    repack_kernel<<<(256 * 64 + 255) / 256, 256>>>(Wp1);
    gemm_tc<<<dim3((NN + 127) / 128, 1), 256>>>(gx2, gW, gP, NN, 64, 256);
    edge_kernel<<<(NE + 7) / 8, 256>>>(ei, ea, Wm1, bm1, Wm2, bm2,
                                       Wp1, bp1, Wp2, bp2, out);
}

// round 6
// speedup vs baseline: 1.5409x; 1.2704x over previous
#include <cuda_runtime.h>
#include <math.h>

#define NN 50000
#define NE 400000
#define DIN 128
#define F 256
#define H 8
#define C 32

// ---------------- scratch (device globals; no allocation) ----------------
__device__ float g_h [NN * F];      // h = x @ W for current layer
__device__ float g_x1[NN * F];      // layer-1 output
__device__ float g_x2[NN * F];      // layer-2 output
__device__ float g_as[NN * H];
__device__ float g_ad[NN * H];
__device__ float g_P [NN * 64];     // [Prow(32) | Pcol(32)] per node
__device__ float g_Wcat[256 * 64];  // repacked Wp1[0:512] as [256][64]
// CSR of incoming real edges (self-loops handled implicitly)
__device__ int g_cnt[NN];
__device__ int g_off[NN + 1];
__device__ int g_cur[NN];
__device__ int g_src[NE];           // src node per CSR slot

// ---------------- tf32 split helpers ----------------
__device__ __forceinline__ void split_tf32(float v, unsigned& hi, unsigned& lo) {
    unsigned h;
    asm("cvt.rna.tf32.f32 %0, %1;" : "=r"(h) : "f"(v));
    float r = v - __uint_as_float(h);
    unsigned l;
    asm("cvt.rna.tf32.f32 %0, %1;" : "=r"(l) : "f"(r));
    hi = h; lo = l;
}

__device__ __forceinline__ void mma_tf32(float* d, const unsigned* a, const unsigned* b) {
    asm volatile(
        "mma.sync.aligned.m16n8k8.row.col.f32.tf32.tf32.f32 "
        "{%0,%1,%2,%3}, {%4,%5,%6,%7}, {%8,%9}, {%0,%1,%2,%3};\n"
        : "+f"(d[0]), "+f"(d[1]), "+f"(d[2]), "+f"(d[3])
        : "r"(a[0]), "r"(a[1]), "r"(a[2]), "r"(a[3]), "r"(b[0]), "r"(b[1]));
}

// ---------------- tensor-core GEMM: C[M,N] = A[M,K] @ B[K,N] ----------------
// Block tile 128x64, 8 warps (4m x 2n), warp tile 32x32, BK=16,
// split-TF32 (3 mma per fragment pair). K%16==0, N%64==0.
__global__ void gemm_tc(const float* __restrict__ A, const float* __restrict__ B,
                        float* __restrict__ Cp, int M, int N, int K) {
    __shared__ float As[128 * 20];
    __shared__ float Bs[16 * 72];

    int tid = threadIdx.x;
    int lane = tid & 31, wid = tid >> 5;
    int wm = wid & 3, wn = wid >> 2;
    int g = lane >> 2, tg = lane & 3;
    int rowBase = blockIdx.x * 128;
    int colBase = blockIdx.y * 64;

    float acc[2][4][4];
#pragma unroll
    for (int i = 0; i < 2; i++)
#pragma unroll
        for (int j = 0; j < 4; j++)
#pragma unroll
            for (int q = 0; q < 4; q++) acc[i][j][q] = 0.f;

    for (int k0 = 0; k0 < K; k0 += 16) {
#pragma unroll
        for (int l = 0; l < 2; l++) {
            int idx = tid + l * 256;
            int row = idx >> 2, c4 = (idx & 3) << 2;
            float4 v = make_float4(0.f, 0.f, 0.f, 0.f);
            if (rowBase + row < M)
                v = *(const float4*)&A[(size_t)(rowBase + row) * K + k0 + c4];
            *(float4*)&As[row * 20 + c4] = v;
        }
        {
            int row = tid >> 4, c4 = (tid & 15) << 2;
            float4 v = *(const float4*)&B[(size_t)(k0 + row) * N + colBase + c4];
            *(float4*)&Bs[row * 72 + c4] = v;
        }
        __syncthreads();

#pragma unroll
        for (int k8 = 0; k8 < 16; k8 += 8) {
            unsigned ahi[2][4], alo[2][4], bhi[4][2], blo[4][2];
#pragma unroll
            for (int i = 0; i < 2; i++) {
                int r0 = wm * 32 + i * 16 + g;
                float v0 = As[r0 * 20 + k8 + tg];
                float v1 = As[(r0 + 8) * 20 + k8 + tg];
                float v2 = As[r0 * 20 + k8 + tg + 4];
                float v3 = As[(r0 + 8) * 20 + k8 + tg + 4];
                split_tf32(v0, ahi[i][0], alo[i][0]);
                split_tf32(v1, ahi[i][1], alo[i][1]);
                split_tf32(v2, ahi[i][2], alo[i][2]);
                split_tf32(v3, ahi[i][3], alo[i][3]);
            }
#pragma unroll
            for (int j = 0; j < 4; j++) {
                int c0 = wn * 32 + j * 8 + g;
                float v0 = Bs[(k8 + tg) * 72 + c0];
                float v1 = Bs[(k8 + tg + 4) * 72 + c0];
                split_tf32(v0, bhi[j][0], blo[j][0]);
                split_tf32(v1, bhi[j][1], blo[j][1]);
            }
#pragma unroll
            for (int i = 0; i < 2; i++)
#pragma unroll
                for (int j = 0; j < 4; j++) {
                    mma_tf32(acc[i][j], alo[i], bhi[j]);
                    mma_tf32(acc[i][j], ahi[i], blo[j]);
                    mma_tf32(acc[i][j], ahi[i], bhi[j]);
                }
        }
        __syncthreads();
    }

#pragma unroll
    for (int i = 0; i < 2; i++) {
        int r = rowBase + wm * 32 + i * 16 + g;
#pragma unroll
        for (int j = 0; j < 4; j++) {
            int c = colBase + wn * 32 + j * 8 + 2 * tg;
            if (r < M) {
                float2 v0 = make_float2(acc[i][j][0], acc[i][j][1]);
                *(float2*)&Cp[(size_t)r * N + c] = v0;
            }
            if (r + 8 < M) {
                float2 v1 = make_float2(acc[i][j][2], acc[i][j][3]);
                *(float2*)&Cp[(size_t)(r + 8) * N + c] = v1;
            }
        }
    }
}

// ---------------- CSR build ----------------
__global__ void csr_zero() {
    int i = blockIdx.x * blockDim.x + threadIdx.x;
    if (i < NN) g_cnt[i] = 0;
}
__global__ void csr_count(const int* __restrict__ ei) {
    int e = blockIdx.x * blockDim.x + threadIdx.x;
    if (e < NE) atomicAdd(&g_cnt[ei[NE + e]], 1);
}
// single-block exclusive scan over 50000 counts (1024 threads)
__global__ void csr_scan() {
    __shared__ int wsum[32];
    __shared__ int carry_s;
    int t = threadIdx.x, lane = t & 31, wid = t >> 5;
    if (t == 0) carry_s = 0;
    __syncthreads();
    for (int base = 0; base < NN; base += 1024) {
        int i = base + t;
        int v = (i < NN) ? g_cnt[i] : 0;
        int x = v;
#pragma unroll
        for (int o = 1; o < 32; o <<= 1) {
            int y = __shfl_up_sync(0xFFFFFFFFu, x, o);
            if (lane >= o) x += y;
        }
        if (lane == 31) wsum[wid] = x;
        __syncthreads();
        if (wid == 0) {
            int s = wsum[lane];
#pragma unroll
            for (int o = 1; o < 32; o <<= 1) {
                int y = __shfl_up_sync(0xFFFFFFFFu, s, o);
                if (lane >= o) s += y;
            }
            wsum[lane] = s;
        }
        __syncthreads();
        int inc = x + (wid > 0 ? wsum[wid - 1] : 0);
        int exc = carry_s + inc - v;
        if (i < NN) { g_off[i] = exc; g_cur[i] = exc; }
        __syncthreads();
        if (t == 1023) carry_s += wsum[31];
        __syncthreads();
    }
    if (t == 0) g_off[NN] = NE;
}
__global__ void csr_fill(const int* __restrict__ ei) {
    int e = blockIdx.x * blockDim.x + threadIdx.x;
    if (e >= NE) return;
    int d = ei[NE + e];
    int pos = atomicAdd(&g_cur[d], 1);
    g_src[pos] = ei[e];
}

// ---------------- alpha_src/alpha_dst: warp per (node, head) ----------------
__global__ void alpha_kernel(const float* __restrict__ a_src, const float* __restrict__ a_dst) {
    int w = (blockIdx.x * blockDim.x + threadIdx.x) >> 5;
    int lane = threadIdx.x & 31;
    if (w >= NN * H) return;
    int n = w >> 3, hh = w & 7;
    float v = g_h[n * F + hh * C + lane];
    float s = v * a_src[hh * C + lane];
    float d = v * a_dst[hh * C + lane];
#pragma unroll
    for (int o = 16; o; o >>= 1) {
        s += __shfl_xor_sync(0xFFFFFFFFu, s, o);
        d += __shfl_xor_sync(0xFFFFFFFFu, d, o);
    }
    if (lane == 0) { g_as[w] = s; g_ad[w] = d; }
}

// ---------------- fused softmax-attention aggregation: warp per dst ----------------
// out[d] = relu( (sum_e exp(e_h - m_h) * h[src]) / (sum_e exp(e_h - m_h)) + b )
__global__ void gat_fused(const float* __restrict__ b, float* __restrict__ out) {
    int w = (blockIdx.x * blockDim.x + threadIdx.x) >> 5;
    int lane = threadIdx.x & 31;
    if (w >= NN) return;
    const int d = w;

    float4 t0 = *(const float4*)&g_ad[d * 8];
    float4 t1 = *(const float4*)&g_ad[d * 8 + 4];
    float adv[8] = {t0.x, t0.y, t0.z, t0.w, t1.x, t1.y, t1.z, t1.w};
    float4 s0 = *(const float4*)&g_as[d * 8];
    float4 s1 = *(const float4*)&g_as[d * 8 + 4];
    float slf[8] = {s0.x, s0.y, s0.z, s0.w, s1.x, s1.y, s1.z, s1.w};

    int beg = g_off[d], end = g_off[d + 1];

    // pass 1: per-head max (edge-parallel across lanes), seeded by self-loop
    float mx[8];
#pragma unroll
    for (int h = 0; h < 8; h++) {
        float e = slf[h] + adv[h];
        mx[h] = (e > 0.f) ? e : 0.2f * e;
    }
    for (int i = beg + lane; i < end; i += 32) {
        int s = g_src[i];
        float4 a0 = *(const float4*)&g_as[s * 8];
        float4 a1 = *(const float4*)&g_as[s * 8 + 4];
        float av[8] = {a0.x, a0.y, a0.z, a0.w, a1.x, a1.y, a1.z, a1.w};
#pragma unroll
        for (int h = 0; h < 8; h++) {
            float e = av[h] + adv[h];
            e = (e > 0.f) ? e : 0.2f * e;
            mx[h] = fmaxf(mx[h], e);
        }
    }
#pragma unroll
    for (int h = 0; h < 8; h++)
#pragma unroll
        for (int o = 16; o; o >>= 1)
            mx[h] = fmaxf(mx[h], __shfl_xor_sync(0xFFFFFFFFu, mx[h], o));

    // pass 2: accumulate numerator (per-lane channel h*32+lane) and denominator
    float num[8], den[8];
#pragma unroll
    for (int h = 0; h < 8; h++) {
        float e = slf[h] + adv[h];
        e = (e > 0.f) ? e : 0.2f * e;
        float ex = expf(e - mx[h]);
        den[h] = ex;
        num[h] = ex * g_h[d * F + h * 32 + lane];
    }
    for (int i = beg; i < end; i++) {
        int s = g_src[i];                       // uniform across warp
        float4 a0 = *(const float4*)&g_as[s * 8];
        float4 a1 = *(const float4*)&g_as[s * 8 + 4];
        float av[8] = {a0.x, a0.y, a0.z, a0.w, a1.x, a1.y, a1.z, a1.w};
        const float* hrow = &g_h[s * F];
#pragma unroll
        for (int h = 0; h < 8; h++) {
            float e = av[h] + adv[h];
            e = (e > 0.f) ? e : 0.2f * e;
            float ex = expf(e - mx[h]);
            den[h] += ex;
            num[h] += ex * hrow[h * 32 + lane];
        }
    }
#pragma unroll
    for (int h = 0; h < 8; h++) {
        float v = num[h] / den[h] + b[h * 32 + lane];
        out[d * F + h * 32 + lane] = (v > 0.f) ? v : 0.f;
    }
}

// ---------------- repack Wp1[0:512,0:32] -> g_Wcat[256][64] ----------------
__global__ void repack_kernel(const float* __restrict__ Wp1) {
    int t = blockIdx.x * blockDim.x + threadIdx.x;
    if (t >= 256 * 64) return;
    int k = t >> 6, j = t & 63;
    g_Wcat[t] = (j < 32) ? Wp1[k * 32 + j] : Wp1[(256 + k) * 32 + (j - 32)];
}

// ---------------- fused edge head: warp per edge ----------------
__global__ void edge_kernel(const int* __restrict__ ei, const float* __restrict__ ea,
                            const float* __restrict__ Wm1, const float* __restrict__ bm1,
                            const float* __restrict__ Wm2, const float* __restrict__ bm2,
                            const float* __restrict__ Wp1, const float* __restrict__ bp1,
                            const float* __restrict__ Wp2, const float* __restrict__ bp2,
                            float* __restrict__ out) {
    __shared__ float sWm1[1024], sWm2[1024], sWpc[1024];
    __shared__ float sbm1[32], sbm2[32], sbp1[32], sWp2[32];
    for (int t = threadIdx.x; t < 1024; t += blockDim.x) {
        sWm1[t] = Wm1[t];
        sWm2[t] = Wm2[t];
        sWpc[t] = Wp1[512 * 32 + t];
    }
    if (threadIdx.x < 32) {
        sbm1[threadIdx.x] = bm1[threadIdx.x];
        sbm2[threadIdx.x] = bm2[threadIdx.x];
        sbp1[threadIdx.x] = bp1[threadIdx.x];
        sWp2[threadIdx.x] = Wp2[threadIdx.x];
    }
    __syncthreads();

    int w = (blockIdx.x * blockDim.x + threadIdx.x) >> 5;
    int lane = threadIdx.x & 31;
    if (w >= NE) return;

    float eav = ea[w * 32 + lane];

    float a1 = sbm1[lane];
#pragma unroll
    for (int k = 0; k < 32; k++)
        a1 += __shfl_sync(0xFFFFFFFFu, eav, k) * sWm1[k * 32 + lane];
    a1 = fmaxf(a1, 0.f);

    float a2 = sbm2[lane];
#pragma unroll
    for (int k = 0; k < 32; k++)
        a2 += __shfl_sync(0xFFFFFFFFu, a1, k) * sWm2[k * 32 + lane];
    a2 = fmaxf(a2, 0.f);

    float q = 0.f;
#pragma unroll
    for (int k = 0; k < 32; k++)
        q += __shfl_sync(0xFFFFFFFFu, a2, k) * sWpc[k * 32 + lane];

    int r = ei[w], c = ei[NE + w];
    float t = g_P[r * 64 + lane] + g_P[c * 64 + 32 + lane] + q + sbp1[lane];
    t = fmaxf(t, 0.f);

    float s = t * sWp2[lane];
#pragma unroll
    for (int o = 16; o; o >>= 1) s += __shfl_xor_sync(0xFFFFFFFFu, s, o);
    if (lane == 0) out[w] = s + bp2[0];
}

// ---------------- host driver ----------------
static void run_gat_layer(const float* xin, int K, const float* W,
                          const float* a_s, const float* a_d, const float* b,
                          float* h_ptr, float* out_ptr) {
    dim3 ggrid((NN + 127) / 128, 4);
    gemm_tc<<<ggrid, 256>>>(xin, W, h_ptr, NN, 256, K);
    alpha_kernel<<<(NN * H * 32 + 255) / 256, 256>>>(a_s, a_d);
    gat_fused<<<(NN * 32 + 255) / 256, 256>>>(b, out_ptr);
}

extern "C" void kernel_launch(void* const* d_in, const int* in_sizes, int n_in,
                              void* d_out, int out_size) {
    const float* x      = (const float*)d_in[0];
    const int*   ei     = (const int*)  d_in[1];
    const float* ea     = (const float*)d_in[2];
    const float* W1     = (const float*)d_in[3];
    const float* a_src1 = (const float*)d_in[4];
    const float* a_dst1 = (const float*)d_in[5];
    const float* b1     = (const float*)d_in[6];
    const float* W2     = (const float*)d_in[7];
    const float* a_src2 = (const float*)d_in[8];
    const float* a_dst2 = (const float*)d_in[9];
    const float* b2     = (const float*)d_in[10];
    const float* Wm1    = (const float*)d_in[11];
    const float* bm1    = (const float*)d_in[12];
    const float* Wm2    = (const float*)d_in[13];
    const float* bm2    = (const float*)d_in[14];
    const float* Wp1    = (const float*)d_in[15];
    const float* bp1    = (const float*)d_in[16];
    const float* Wp2    = (const float*)d_in[17];
    const float* bp2    = (const float*)d_in[18];
    float* out = (float*)d_out;

    float *gh, *gx1, *gx2, *gP, *gW;
    cudaGetSymbolAddress((void**)&gh,  g_h);
    cudaGetSymbolAddress((void**)&gx1, g_x1);
    cudaGetSymbolAddress((void**)&gx2, g_x2);
    cudaGetSymbolAddress((void**)&gP,  g_P);
    cudaGetSymbolAddress((void**)&gW,  g_Wcat);

    // build CSR (dst-bucketed src lists) once per launch
    csr_zero <<<(NN + 255) / 256, 256>>>();
    csr_count<<<(NE + 255) / 256, 256>>>(ei);
    csr_scan <<<1, 1024>>>();
    csr_fill <<<(NE + 255) / 256, 256>>>(ei);

    run_gat_layer(x,   DIN, W1, a_src1, a_dst1, b1, gh, gx1);
    run_gat_layer(gx1, F,   W2, a_src2, a_dst2, b2, gh, gx2);

    repack_kernel<<<(256 * 64 + 255) / 256, 256>>>(Wp1);
    gemm_tc<<<dim3((NN + 127) / 128, 1), 256>>>(gx2, gW, gP, NN, 64, 256);
    edge_kernel<<<(NE + 7) / 8, 256>>>(ei, ea, Wm1, bm1, Wm2, bm2,
                                       Wp1, bp1, Wp2, bp2, out);
}

// round 8
// speedup vs baseline: 1.6802x; 1.0904x over previous
#include <cuda_runtime.h>
#include <cuda_bf16.h>
#include <math.h>
#include <stdint.h>

#define NN 50000
#define NE 400000
#define DIN 128
#define F 256
#define H 8

// ---------------- scratch (device globals; no allocation) ----------------
__device__ float g_h [NN * F];      // h = x @ W for current layer (fp32)
__device__ float g_as[NN * H];
__device__ float g_ad[NN * H];
__device__ float g_P [NN * 64];     // [Prow(32) | Pcol(32)] per node
// split bf16 activations
__device__ __nv_bfloat16 g_xh[NN * DIN], g_xl[NN * DIN];
__device__ __nv_bfloat16 g_y1h[NN * F],  g_y1l[NN * F];
__device__ __nv_bfloat16 g_y2h[NN * F],  g_y2l[NN * F];
// split+transposed weights [N][K] K-major
__device__ __nv_bfloat16 g_w1h[F * DIN], g_w1l[F * DIN];
__device__ __nv_bfloat16 g_w2h[F * F],   g_w2l[F * F];
__device__ __nv_bfloat16 g_wch[64 * F],  g_wcl[64 * F];
// CSR of incoming real edges
__device__ int g_cnt[NN];
__device__ int g_off[NN + 1];
__device__ int g_cur[NN];
__device__ int g_src[NE];

// ---------------- bf16 mma helper ----------------
__device__ __forceinline__ void mma_bf16(float* d, const uint32_t* a, const uint32_t* b) {
    asm volatile(
        "mma.sync.aligned.m16n8k16.row.col.f32.bf16.bf16.f32 "
        "{%0,%1,%2,%3}, {%4,%5,%6,%7}, {%8,%9}, {%0,%1,%2,%3};\n"
        : "+f"(d[0]), "+f"(d[1]), "+f"(d[2]), "+f"(d[3])
        : "r"(a[0]), "r"(a[1]), "r"(a[2]), "r"(a[3]), "r"(b[0]), "r"(b[1]));
}

// ---------------- split-bf16 tensor GEMM: C[M,Ntot] = A[M,K] @ B^T ----------------
// A: [M][K] split hi/lo bf16. B: [Ntot][K] split hi/lo bf16 (K-major).
// Block tile 128x64, 8 warps (4m x 2n), warp tile 32x32, BK=32.
// 3-term split: hh + hl + lh. K % 32 == 0.
__global__ void __launch_bounds__(256) gemm_bf16(
        const __nv_bfloat16* __restrict__ Ah, const __nv_bfloat16* __restrict__ Al,
        const __nv_bfloat16* __restrict__ Bh, const __nv_bfloat16* __restrict__ Bl,
        float* __restrict__ C, int M, int Ntot, int K) {
    __shared__ __nv_bfloat16 sAh[128 * 40], sAl[128 * 40];   // stride 40 bf16 (20 u32)
    __shared__ __nv_bfloat16 sBh[64 * 40],  sBl[64 * 40];

    int tid = threadIdx.x;
    int lane = tid & 31, wid = tid >> 5;
    int wm = wid & 3, wn = wid >> 2;
    int g = lane >> 2, tg = lane & 3;
    int rowBase = blockIdx.x * 128;
    int colBase = blockIdx.y * 64;

    float acc[2][4][4];
#pragma unroll
    for (int i = 0; i < 2; i++)
#pragma unroll
        for (int j = 0; j < 4; j++)
#pragma unroll
            for (int q = 0; q < 4; q++) acc[i][j][q] = 0.f;

    const uint32_t* A32h = (const uint32_t*)sAh;
    const uint32_t* A32l = (const uint32_t*)sAl;
    const uint32_t* B32h = (const uint32_t*)sBh;
    const uint32_t* B32l = (const uint32_t*)sBl;

    for (int k0 = 0; k0 < K; k0 += 32) {
        // load A tile: 128 rows x 32 bf16 (hi+lo), uint4 = 8 bf16
#pragma unroll
        for (int l = 0; l < 2; l++) {
            int idx = tid + l * 256;              // 0..511
            int r = idx >> 2, c8 = (idx & 3) << 3;
            uint4 vh = make_uint4(0, 0, 0, 0), vl = make_uint4(0, 0, 0, 0);
            int gr = rowBase + r;
            if (gr < M) {
                vh = *(const uint4*)&Ah[(size_t)gr * K + k0 + c8];
                vl = *(const uint4*)&Al[(size_t)gr * K + k0 + c8];
            }
            *(uint4*)&sAh[r * 40 + c8] = vh;
            *(uint4*)&sAl[r * 40 + c8] = vl;
        }
        // load B tile: 64 rows x 32 bf16 (hi+lo)
        {
            int r = tid >> 2, c8 = (tid & 3) << 3;   // 256 threads cover 64x32
            int gn = colBase + r;
            uint4 vh = *(const uint4*)&Bh[(size_t)gn * K + k0 + c8];
            uint4 vl = *(const uint4*)&Bl[(size_t)gn * K + k0 + c8];
            *(uint4*)&sBh[r * 40 + c8] = vh;
            *(uint4*)&sBl[r * 40 + c8] = vl;
        }
        __syncthreads();

#pragma unroll
        for (int ks = 0; ks < 2; ks++) {           // two k16 steps
            int ko = ks << 3;                      // u32 offset within row
            uint32_t ah[2][4], al[2][4], bh[4][2], bl[4][2];
#pragma unroll
            for (int i = 0; i < 2; i++) {
                int r = wm * 32 + i * 16 + g;
                ah[i][0] = A32h[r * 20 + ko + tg];
                ah[i][1] = A32h[(r + 8) * 20 + ko + tg];
                ah[i][2] = A32h[r * 20 + ko + 4 + tg];
                ah[i][3] = A32h[(r + 8) * 20 + ko + 4 + tg];
                al[i][0] = A32l[r * 20 + ko + tg];
                al[i][1] = A32l[(r + 8) * 20 + ko + tg];
                al[i][2] = A32l[r * 20 + ko + 4 + tg];
                al[i][3] = A32l[(r + 8) * 20 + ko + 4 + tg];
            }
#pragma unroll
            for (int j = 0; j < 4; j++) {
                int n = wn * 32 + j * 8 + g;
                bh[j][0] = B32h[n * 20 + ko + tg];
                bh[j][1] = B32h[n * 20 + ko + 4 + tg];
                bl[j][0] = B32l[n * 20 + ko + tg];
                bl[j][1] = B32l[n * 20 + ko + 4 + tg];
            }
#pragma unroll
            for (int i = 0; i < 2; i++)
#pragma unroll
                for (int j = 0; j < 4; j++) {
                    mma_bf16(acc[i][j], ah[i], bl[j]);   // hi*lo
                    mma_bf16(acc[i][j], al[i], bh[j]);   // lo*hi
                    mma_bf16(acc[i][j], ah[i], bh[j]);   // hi*hi
                }
        }
        __syncthreads();
    }

    // epilogue: m16n8 accum mapping c0=(g,2tg) c1=(g,2tg+1) c2=(g+8,2tg) c3=(g+8,2tg+1)
#pragma unroll
    for (int i = 0; i < 2; i++) {
        int r = rowBase + wm * 32 + i * 16 + g;
#pragma unroll
        for (int j = 0; j < 4; j++) {
            int c = colBase + wn * 32 + j * 8 + 2 * tg;
            if (r < M)
                *(float2*)&C[(size_t)r * Ntot + c] = make_float2(acc[i][j][0], acc[i][j][1]);
            if (r + 8 < M)
                *(float2*)&C[(size_t)(r + 8) * Ntot + c] = make_float2(acc[i][j][2], acc[i][j][3]);
        }
    }
}

// ---------------- prep kernels ----------------
__global__ void fsplit(const float* __restrict__ s, __nv_bfloat16* __restrict__ h,
                       __nv_bfloat16* __restrict__ l, int n) {
    int i = blockIdx.x * blockDim.x + threadIdx.x;
    if (i >= n) return;
    float v = s[i];
    __nv_bfloat16 hi = __float2bfloat16(v);
    h[i] = hi;
    l[i] = __float2bfloat16(v - __bfloat162float(hi));
}
// transpose+split weights: W[K][N] -> T[N][K]
__global__ void wprep(const float* __restrict__ W, __nv_bfloat16* __restrict__ th,
                      __nv_bfloat16* __restrict__ tl, int K, int N) {
    int i = blockIdx.x * blockDim.x + threadIdx.x;
    if (i >= K * N) return;
    int k = i / N, n = i % N;
    float v = W[i];
    __nv_bfloat16 hi = __float2bfloat16(v);
    th[n * K + k] = hi;
    tl[n * K + k] = __float2bfloat16(v - __bfloat162float(hi));
}
// Wcat^T[j][k] from Wp1 (cols 0..511)
__global__ void wcatprep(const float* __restrict__ Wp1) {
    int i = blockIdx.x * blockDim.x + threadIdx.x;
    if (i >= 64 * 256) return;
    int j = i / 256, k = i % 256;
    float v = (j < 32) ? Wp1[k * 32 + j] : Wp1[(256 + k) * 32 + (j - 32)];
    __nv_bfloat16 hi = __float2bfloat16(v);
    g_wch[i] = hi;
    g_wcl[i] = __float2bfloat16(v - __bfloat162float(hi));
}

// ---------------- CSR build ----------------
__global__ void csr_zero() {
    int i = blockIdx.x * blockDim.x + threadIdx.x;
    if (i < NN) g_cnt[i] = 0;
}
__global__ void csr_count(const int* __restrict__ ei) {
    int e = blockIdx.x * blockDim.x + threadIdx.x;
    if (e < NE) atomicAdd(&g_cnt[ei[NE + e]], 1);
}
__global__ void csr_scan() {
    __shared__ int wsum[32];
    __shared__ int carry_s;
    int t = threadIdx.x, lane = t & 31, wid = t >> 5;
    if (t == 0) carry_s = 0;
    __syncthreads();
    for (int base = 0; base < NN; base += 1024) {
        int i = base + t;
        int v = (i < NN) ? g_cnt[i] : 0;
        int x = v;
#pragma unroll
        for (int o = 1; o < 32; o <<= 1) {
            int y = __shfl_up_sync(0xFFFFFFFFu, x, o);
            if (lane >= o) x += y;
        }
        if (lane == 31) wsum[wid] = x;
        __syncthreads();
        if (wid == 0) {
            int s = wsum[lane];
#pragma unroll
            for (int o = 1; o < 32; o <<= 1) {
                int y = __shfl_up_sync(0xFFFFFFFFu, s, o);
                if (lane >= o) s += y;
            }
            wsum[lane] = s;
        }
        __syncthreads();
        int inc = x + (wid > 0 ? wsum[wid - 1] : 0);
        int exc = carry_s + inc - v;
        if (i < NN) { g_off[i] = exc; g_cur[i] = exc; }
        __syncthreads();
        if (t == 1023) carry_s += wsum[31];
        __syncthreads();
    }
    if (t == 0) g_off[NN] = NE;
}
__global__ void csr_fill(const int* __restrict__ ei) {
    int e = blockIdx.x * blockDim.x + threadIdx.x;
    if (e >= NE) return;
    int d = ei[NE + e];
    int pos = atomicAdd(&g_cur[d], 1);
    g_src[pos] = ei[e];
}

// ---------------- alpha_src/alpha_dst: warp per (node, head) ----------------
__global__ void alpha_kernel(const float* __restrict__ a_src, const float* __restrict__ a_dst) {
    int w = (blockIdx.x * blockDim.x + threadIdx.x) >> 5;
    int lane = threadIdx.x & 31;
    if (w >= NN * H) return;
    int n = w >> 3, hh = w & 7;
    float v = g_h[n * F + hh * 32 + lane];
    float s = v * a_src[hh * 32 + lane];
    float d = v * a_dst[hh * 32 + lane];
#pragma unroll
    for (int o = 16; o; o >>= 1) {
        s += __shfl_xor_sync(0xFFFFFFFFu, s, o);
        d += __shfl_xor_sync(0xFFFFFFFFu, d, o);
    }
    if (lane == 0) { g_as[w] = s; g_ad[w] = d; }
}

// ---------------- fused softmax-attention aggregation: warp per dst ----------------
// writes relu(agg + b) split into hi/lo bf16 for the next GEMM
__global__ void gat_fused(const float* __restrict__ b,
                          __nv_bfloat16* __restrict__ oh, __nv_bfloat16* __restrict__ ol) {
    int w = (blockIdx.x * blockDim.x + threadIdx.x) >> 5;
    int lane = threadIdx.x & 31;
    if (w >= NN) return;
    const int d = w;

    float4 t0 = *(const float4*)&g_ad[d * 8];
    float4 t1 = *(const float4*)&g_ad[d * 8 + 4];
    float adv[8] = {t0.x, t0.y, t0.z, t0.w, t1.x, t1.y, t1.z, t1.w};
    float4 s0 = *(const float4*)&g_as[d * 8];
    float4 s1 = *(const float4*)&g_as[d * 8 + 4];
    float slf[8] = {s0.x, s0.y, s0.z, s0.w, s1.x, s1.y, s1.z, s1.w};

    int beg = g_off[d], end = g_off[d + 1];

    float mx[8];
#pragma unroll
    for (int h = 0; h < 8; h++) {
        float e = slf[h] + adv[h];
        mx[h] = (e > 0.f) ? e : 0.2f * e;
    }
    for (int i = beg + lane; i < end; i += 32) {
        int s = g_src[i];
        float4 a0 = *(const float4*)&g_as[s * 8];
        float4 a1 = *(const float4*)&g_as[s * 8 + 4];
        float av[8] = {a0.x, a0.y, a0.z, a0.w, a1.x, a1.y, a1.z, a1.w};
#pragma unroll
        for (int h = 0; h < 8; h++) {
            float e = av[h] + adv[h];
            e = (e > 0.f) ? e : 0.2f * e;
            mx[h] = fmaxf(mx[h], e);
        }
    }
#pragma unroll
    for (int h = 0; h < 8; h++)
#pragma unroll
        for (int o = 16; o; o >>= 1)
            mx[h] = fmaxf(mx[h], __shfl_xor_sync(0xFFFFFFFFu, mx[h], o));

    float num[8], den[8];
#pragma unroll
    for (int h = 0; h < 8; h++) {
        float e = slf[h] + adv[h];
        e = (e > 0.f) ? e : 0.2f * e;
        float ex = expf(e - mx[h]);
        den[h] = ex;
        num[h] = ex * g_h[d * F + h * 32 + lane];
    }
    for (int i = beg; i < end; i++) {
        int s = g_src[i];
        float4 a0 = *(const float4*)&g_as[s * 8];
        float4 a1 = *(const float4*)&g_as[s * 8 + 4];
        float av[8] = {a0.x, a0.y, a0.z, a0.w, a1.x, a1.y, a1.z, a1.w};
        const float* hrow = &g_h[s * F];
#pragma unroll
        for (int h = 0; h < 8; h++) {
            float e = av[h] + adv[h];
            e = (e > 0.f) ? e : 0.2f * e;
            float ex = expf(e - mx[h]);
            den[h] += ex;
            num[h] += ex * hrow[h * 32 + lane];
        }
    }
#pragma unroll
    for (int h = 0; h < 8; h++) {
        float v = num[h] / den[h] + b[h * 32 + lane];
        v = (v > 0.f) ? v : 0.f;
        __nv_bfloat16 hi = __float2bfloat16(v);
        oh[d * F + h * 32 + lane] = hi;
        ol[d * F + h * 32 + lane] = __float2bfloat16(v - __bfloat162float(hi));
    }
}

// ---------------- fused edge head: warp per edge ----------------
__global__ void edge_kernel(const int* __restrict__ ei, const float* __restrict__ ea,
                            const float* __restrict__ Wm1, const float* __restrict__ bm1,
                            const float* __restrict__ Wm2, const float* __restrict__ bm2,
                            const float* __restrict__ Wp1, const float* __restrict__ bp1,
                            const float* __restrict__ Wp2, const float* __restrict__ bp2,
                            float* __restrict__ out) {
    __shared__ float sWm1[1024], sWm2[1024], sWpc[1024];
    __shared__ float sbm1[32], sbm2[32], sbp1[32], sWp2[32];
    for (int t = threadIdx.x; t < 1024; t += blockDim.x) {
        sWm1[t] = Wm1[t];
        sWm2[t] = Wm2[t];
        sWpc[t] = Wp1[512 * 32 + t];
    }
    if (threadIdx.x < 32) {
        sbm1[threadIdx.x] = bm1[threadIdx.x];
        sbm2[threadIdx.x] = bm2[threadIdx.x];
        sbp1[threadIdx.x] = bp1[threadIdx.x];
        sWp2[threadIdx.x] = Wp2[threadIdx.x];
    }
    __syncthreads();

    int w = (blockIdx.x * blockDim.x + threadIdx.x) >> 5;
    int lane = threadIdx.x & 31;
    if (w >= NE) return;

    float eav = ea[w * 32 + lane];

    float a1 = sbm1[lane];
#pragma unroll
    for (int k = 0; k < 32; k++)
        a1 += __shfl_sync(0xFFFFFFFFu, eav, k) * sWm1[k * 32 + lane];
    a1 = fmaxf(a1, 0.f);

    float a2 = sbm2[lane];
#pragma unroll
    for (int k = 0; k < 32; k++)
        a2 += __shfl_sync(0xFFFFFFFFu, a1, k) * sWm2[k * 32 + lane];
    a2 = fmaxf(a2, 0.f);

    float q = 0.f;
#pragma unroll
    for (int k = 0; k < 32; k++)
        q += __shfl_sync(0xFFFFFFFFu, a2, k) * sWpc[k * 32 + lane];

    int r = ei[w], c = ei[NE + w];
    float t = g_P[r * 64 + lane] + g_P[c * 64 + 32 + lane] + q + sbp1[lane];
    t = fmaxf(t, 0.f);

    float s = t * sWp2[lane];
#pragma unroll
    for (int o = 16; o; o >>= 1) s += __shfl_xor_sync(0xFFFFFFFFu, s, o);
    if (lane == 0) out[w] = s + bp2[0];
}

// ---------------- host driver ----------------
extern "C" void kernel_launch(void* const* d_in, const int* in_sizes, int n_in,
                              void* d_out, int out_size) {
    const float* x      = (const float*)d_in[0];
    const int*   ei     = (const int*)  d_in[1];
    const float* ea     = (const float*)d_in[2];
    const float* W1     = (const float*)d_in[3];
    const float* a_src1 = (const float*)d_in[4];
    const float* a_dst1 = (const float*)d_in[5];
    const float* b1     = (const float*)d_in[6];
    const float* W2     = (const float*)d_in[7];
    const float* a_src2 = (const float*)d_in[8];
    const float* a_dst2 = (const float*)d_in[9];
    const float* b2     = (const float*)d_in[10];
    const float* Wm1    = (const float*)d_in[11];
    const float* bm1    = (const float*)d_in[12];
    const float* Wm2    = (const float*)d_in[13];
    const float* bm2    = (const float*)d_in[14];
    const float* Wp1    = (const float*)d_in[15];
    const float* bp1    = (const float*)d_in[16];
    const float* Wp2    = (const float*)d_in[17];
    const float* bp2    = (const float*)d_in[18];
    float* out = (float*)d_out;

    float *gh, *gP;
    __nv_bfloat16 *xh, *xl, *y1h, *y1l, *y2h, *y2l, *w1h, *w1l, *w2h, *w2l, *wch, *wcl;
    cudaGetSymbolAddress((void**)&gh,  g_h);
    cudaGetSymbolAddress((void**)&gP,  g_P);
    cudaGetSymbolAddress((void**)&xh,  g_xh);  cudaGetSymbolAddress((void**)&xl,  g_xl);
    cudaGetSymbolAddress((void**)&y1h, g_y1h); cudaGetSymbolAddress((void**)&y1l, g_y1l);
    cudaGetSymbolAddress((void**)&y2h, g_y2h); cudaGetSymbolAddress((void**)&y2l, g_y2l);
    cudaGetSymbolAddress((void**)&w1h, g_w1h); cudaGetSymbolAddress((void**)&w1l, g_w1l);
    cudaGetSymbolAddress((void**)&w2h, g_w2h); cudaGetSymbolAddress((void**)&w2l, g_w2l);
    cudaGetSymbolAddress((void**)&wch, g_wch); cudaGetSymbolAddress((void**)&wcl, g_wcl);

    // CSR
    csr_zero <<<(NN + 255) / 256, 256>>>();
    csr_count<<<(NE + 255) / 256, 256>>>(ei);
    csr_scan <<<1, 1024>>>();
    csr_fill <<<(NE + 255) / 256, 256>>>(ei);

    // prep: split x, transpose+split weights
    fsplit  <<<(NN * DIN + 255) / 256, 256>>>(x, xh, xl, NN * DIN);
    wprep   <<<(DIN * F + 255) / 256, 256>>>(W1, w1h, w1l, DIN, F);
    wprep   <<<(F * F + 255) / 256, 256>>>(W2, w2h, w2l, F, F);
    wcatprep<<<(64 * F + 255) / 256, 256>>>(Wp1);

    const int MT = (NN + 127) / 128;   // 391

    // layer 1
    gemm_bf16<<<dim3(MT, 4), 256>>>(xh, xl, w1h, w1l, gh, NN, F, DIN);
    alpha_kernel<<<(NN * H * 32 + 255) / 256, 256>>>(a_src1, a_dst1);
    gat_fused<<<(NN * 32 + 255) / 256, 256>>>(b1, y1h, y1l);

    // layer 2
    gemm_bf16<<<dim3(MT, 4), 256>>>(y1h, y1l, w2h, w2l, gh, NN, F, F);
    alpha_kernel<<<(NN * H * 32 + 255) / 256, 256>>>(a_src2, a_dst2);
    gat_fused<<<(NN * 32 + 255) / 256, 256>>>(b2, y2h, y2l);

    // P projection + edge head
    gemm_bf16<<<dim3(MT, 1), 256>>>(y2h, y2l, wch, wcl, gP, NN, 64, F);
    edge_kernel<<<(NE + 7) / 8, 256>>>(ei, ea, Wm1, bm1, Wm2, bm2,
                                       Wp1, bp1, Wp2, bp2, out);
}

// round 10
// speedup vs baseline: 1.8051x; 1.0744x over previous
#include <cuda_runtime.h>
#include <cuda_bf16.h>
#include <math.h>
#include <stdint.h>

#define NN 50000
#define NE 400000
#define DIN 128
#define F 256
#define H 8

// ---------------- scratch (device globals; no allocation) ----------------
__device__ float g_h [NN * F];      // h = x @ W for current layer (fp32)
__device__ float g_as[NN * H];
__device__ float g_ad[NN * H];
__device__ float g_P [NN * 64];     // [Prow(32) | Pcol(32)] per node
// split bf16 activations
__device__ __nv_bfloat16 g_xh[NN * DIN], g_xl[NN * DIN];
__device__ __nv_bfloat16 g_y1h[NN * F],  g_y1l[NN * F];
__device__ __nv_bfloat16 g_y2h[NN * F],  g_y2l[NN * F];
// split+transposed weights [N][K] K-major
__device__ __nv_bfloat16 g_w1h[F * DIN], g_w1l[F * DIN];
__device__ __nv_bfloat16 g_w2h[F * F],   g_w2l[F * F];
__device__ __nv_bfloat16 g_wch[64 * F],  g_wcl[64 * F];
// CSR of incoming real edges
__device__ int g_cnt[NN];
__device__ int g_off[NN + 1];
__device__ int g_cur[NN];
__device__ int g_src[NE];

// ---------------- bf16 mma helper ----------------
__device__ __forceinline__ void mma_bf16(float* d, const uint32_t* a, const uint32_t* b) {
    asm volatile(
        "mma.sync.aligned.m16n8k16.row.col.f32.bf16.bf16.f32 "
        "{%0,%1,%2,%3}, {%4,%5,%6,%7}, {%8,%9}, {%0,%1,%2,%3};\n"
        : "+f"(d[0]), "+f"(d[1]), "+f"(d[2]), "+f"(d[3])
        : "r"(a[0]), "r"(a[1]), "r"(a[2]), "r"(a[3]), "r"(b[0]), "r"(b[1]));
}

// ---------------- split-bf16 tensor GEMM: C[M,Ntot] = A[M,K] @ B^T ----------------
// Block tile 128x64, 8 warps (4m x 2n), warp tile 32x32, BK=32, 3-term split.
__global__ void __launch_bounds__(256) gemm_bf16(
        const __nv_bfloat16* __restrict__ Ah, const __nv_bfloat16* __restrict__ Al,
        const __nv_bfloat16* __restrict__ Bh, const __nv_bfloat16* __restrict__ Bl,
        float* __restrict__ C, int M, int Ntot, int K) {
    __shared__ __nv_bfloat16 sAh[128 * 40], sAl[128 * 40];
    __shared__ __nv_bfloat16 sBh[64 * 40],  sBl[64 * 40];

    int tid = threadIdx.x;
    int lane = tid & 31, wid = tid >> 5;
    int wm = wid & 3, wn = wid >> 2;
    int g = lane >> 2, tg = lane & 3;
    int rowBase = blockIdx.x * 128;
    int colBase = blockIdx.y * 64;

    float acc[2][4][4];
#pragma unroll
    for (int i = 0; i < 2; i++)
#pragma unroll
        for (int j = 0; j < 4; j++)
#pragma unroll
            for (int q = 0; q < 4; q++) acc[i][j][q] = 0.f;

    const uint32_t* A32h = (const uint32_t*)sAh;
    const uint32_t* A32l = (const uint32_t*)sAl;
    const uint32_t* B32h = (const uint32_t*)sBh;
    const uint32_t* B32l = (const uint32_t*)sBl;

    for (int k0 = 0; k0 < K; k0 += 32) {
#pragma unroll
        for (int l = 0; l < 2; l++) {
            int idx = tid + l * 256;
            int r = idx >> 2, c8 = (idx & 3) << 3;
            uint4 vh = make_uint4(0, 0, 0, 0), vl = make_uint4(0, 0, 0, 0);
            int gr = rowBase + r;
            if (gr < M) {
                vh = *(const uint4*)&Ah[(size_t)gr * K + k0 + c8];
                vl = *(const uint4*)&Al[(size_t)gr * K + k0 + c8];
            }
            *(uint4*)&sAh[r * 40 + c8] = vh;
            *(uint4*)&sAl[r * 40 + c8] = vl;
        }
        {
            int r = tid >> 2, c8 = (tid & 3) << 3;
            int gn = colBase + r;
            uint4 vh = *(const uint4*)&Bh[(size_t)gn * K + k0 + c8];
            uint4 vl = *(const uint4*)&Bl[(size_t)gn * K + k0 + c8];
            *(uint4*)&sBh[r * 40 + c8] = vh;
            *(uint4*)&sBl[r * 40 + c8] = vl;
        }
        __syncthreads();

#pragma unroll
        for (int ks = 0; ks < 2; ks++) {
            int ko = ks << 3;
            uint32_t ah[2][4], al[2][4], bh[4][2], bl[4][2];
#pragma unroll
            for (int i = 0; i < 2; i++) {
                int r = wm * 32 + i * 16 + g;
                ah[i][0] = A32h[r * 20 + ko + tg];
                ah[i][1] = A32h[(r + 8) * 20 + ko + tg];
                ah[i][2] = A32h[r * 20 + ko + 4 + tg];
                ah[i][3] = A32h[(r + 8) * 20 + ko + 4 + tg];
                al[i][0] = A32l[r * 20 + ko + tg];
                al[i][1] = A32l[(r + 8) * 20 + ko + tg];
                al[i][2] = A32l[r * 20 + ko + 4 + tg];
                al[i][3] = A32l[(r + 8) * 20 + ko + 4 + tg];
            }
#pragma unroll
            for (int j = 0; j < 4; j++) {
                int n = wn * 32 + j * 8 + g;
                bh[j][0] = B32h[n * 20 + ko + tg];
                bh[j][1] = B32h[n * 20 + ko + 4 + tg];
                bl[j][0] = B32l[n * 20 + ko + tg];
                bl[j][1] = B32l[n * 20 + ko + 4 + tg];
            }
#pragma unroll
            for (int i = 0; i < 2; i++)
#pragma unroll
                for (int j = 0; j < 4; j++) {
                    mma_bf16(acc[i][j], ah[i], bl[j]);
                    mma_bf16(acc[i][j], al[i], bh[j]);
                    mma_bf16(acc[i][j], ah[i], bh[j]);
                }
        }
        __syncthreads();
    }

#pragma unroll
    for (int i = 0; i < 2; i++) {
        int r = rowBase + wm * 32 + i * 16 + g;
#pragma unroll
        for (int j = 0; j < 4; j++) {
            int c = colBase + wn * 32 + j * 8 + 2 * tg;
            if (r < M)
                *(float2*)&C[(size_t)r * Ntot + c] = make_float2(acc[i][j][0], acc[i][j][1]);
            if (r + 8 < M)
                *(float2*)&C[(size_t)(r + 8) * Ntot + c] = make_float2(acc[i][j][2], acc[i][j][3]);
        }
    }
}

// ---------------- prep kernels ----------------
__global__ void fsplit(const float* __restrict__ s, __nv_bfloat16* __restrict__ h,
                       __nv_bfloat16* __restrict__ l, int n) {
    int i = blockIdx.x * blockDim.x + threadIdx.x;
    if (i >= n) return;
    float v = s[i];
    __nv_bfloat16 hi = __float2bfloat16(v);
    h[i] = hi;
    l[i] = __float2bfloat16(v - __bfloat162float(hi));
}
__global__ void wprep(const float* __restrict__ W, __nv_bfloat16* __restrict__ th,
                      __nv_bfloat16* __restrict__ tl, int K, int N) {
    int i = blockIdx.x * blockDim.x + threadIdx.x;
    if (i >= K * N) return;
    int k = i / N, n = i % N;
    float v = W[i];
    __nv_bfloat16 hi = __float2bfloat16(v);
    th[n * K + k] = hi;
    tl[n * K + k] = __float2bfloat16(v - __bfloat162float(hi));
}
__global__ void wcatprep(const float* __restrict__ Wp1) {
    int i = blockIdx.x * blockDim.x + threadIdx.x;
    if (i >= 64 * 256) return;
    int j = i / 256, k = i % 256;
    float v = (j < 32) ? Wp1[k * 32 + j] : Wp1[(256 + k) * 32 + (j - 32)];
    __nv_bfloat16 hi = __float2bfloat16(v);
    g_wch[i] = hi;
    g_wcl[i] = __float2bfloat16(v - __bfloat162float(hi));
}

// ---------------- CSR build ----------------
__global__ void csr_zero() {
    int i = blockIdx.x * blockDim.x + threadIdx.x;
    if (i < NN) g_cnt[i] = 0;
}
__global__ void csr_count(const int* __restrict__ ei) {
    int e = blockIdx.x * blockDim.x + threadIdx.x;
    if (e < NE) atomicAdd(&g_cnt[ei[NE + e]], 1);
}
__global__ void csr_scan() {
    __shared__ int wsum[32];
    __shared__ int carry_s;
    int t = threadIdx.x, lane = t & 31, wid = t >> 5;
    if (t == 0) carry_s = 0;
    __syncthreads();
    for (int base = 0; base < NN; base += 1024) {
        int i = base + t;
        int v = (i < NN) ? g_cnt[i] : 0;
        int x = v;
#pragma unroll
        for (int o = 1; o < 32; o <<= 1) {
            int y = __shfl_up_sync(0xFFFFFFFFu, x, o);
            if (lane >= o) x += y;
        }
        if (lane == 31) wsum[wid] = x;
        __syncthreads();
        if (wid == 0) {
            int s = wsum[lane];
#pragma unroll
            for (int o = 1; o < 32; o <<= 1) {
                int y = __shfl_up_sync(0xFFFFFFFFu, s, o);
                if (lane >= o) s += y;
            }
            wsum[lane] = s;
        }
        __syncthreads();
        int inc = x + (wid > 0 ? wsum[wid - 1] : 0);
        int exc = carry_s + inc - v;
        if (i < NN) { g_off[i] = exc; g_cur[i] = exc; }
        __syncthreads();
        if (t == 1023) carry_s += wsum[31];
        __syncthreads();
    }
    if (t == 0) g_off[NN] = NE;
}
__global__ void csr_fill(const int* __restrict__ ei) {
    int e = blockIdx.x * blockDim.x + threadIdx.x;
    if (e >= NE) return;
    int d = ei[NE + e];
    int pos = atomicAdd(&g_cur[d], 1);
    g_src[pos] = ei[e];
}

// ---------------- alpha_src/alpha_dst: warp per (node, head) ----------------
__global__ void alpha_kernel(const float* __restrict__ a_src, const float* __restrict__ a_dst) {
    int w = (blockIdx.x * blockDim.x + threadIdx.x) >> 5;
    int lane = threadIdx.x & 31;
    if (w >= NN * H) return;
    int n = w >> 3, hh = w & 7;
    float v = g_h[n * F + hh * 32 + lane];
    float s = v * a_src[hh * 32 + lane];
    float d = v * a_dst[hh * 32 + lane];
#pragma unroll
    for (int o = 16; o; o >>= 1) {
        s += __shfl_xor_sync(0xFFFFFFFFu, s, o);
        d += __shfl_xor_sync(0xFFFFFFFFu, d, o);
    }
    if (lane == 0) { g_as[w] = s; g_ad[w] = d; }
}

// ---------------- fused softmax-attention aggregation: warp per dst ----------------
// Pass 2 restructured: coefficients computed lane-parallel (one edge per lane),
// broadcast via shfl during the serial accumulation -> 32x fewer expf.
__global__ void gat_fused(const float* __restrict__ b,
                          __nv_bfloat16* __restrict__ oh, __nv_bfloat16* __restrict__ ol) {
    int w = (blockIdx.x * blockDim.x + threadIdx.x) >> 5;
    int lane = threadIdx.x & 31;
    if (w >= NN) return;
    const int d = w;

    float4 t0 = *(const float4*)&g_ad[d * 8];
    float4 t1 = *(const float4*)&g_ad[d * 8 + 4];
    float adv[8] = {t0.x, t0.y, t0.z, t0.w, t1.x, t1.y, t1.z, t1.w};
    float4 s0 = *(const float4*)&g_as[d * 8];
    float4 s1 = *(const float4*)&g_as[d * 8 + 4];
    float slf[8] = {s0.x, s0.y, s0.z, s0.w, s1.x, s1.y, s1.z, s1.w};

    int beg = g_off[d], end = g_off[d + 1];

    // pass 1: per-head max (edge-parallel across lanes), seeded by self-loop
    float mx[8];
#pragma unroll
    for (int h = 0; h < 8; h++) {
        float e = slf[h] + adv[h];
        mx[h] = (e > 0.f) ? e : 0.2f * e;
    }
    for (int i = beg + lane; i < end; i += 32) {
        int s = g_src[i];
        float4 a0 = *(const float4*)&g_as[s * 8];
        float4 a1 = *(const float4*)&g_as[s * 8 + 4];
        float av[8] = {a0.x, a0.y, a0.z, a0.w, a1.x, a1.y, a1.z, a1.w};
#pragma unroll
        for (int h = 0; h < 8; h++) {
            float e = av[h] + adv[h];
            e = (e > 0.f) ? e : 0.2f * e;
            mx[h] = fmaxf(mx[h], e);
        }
    }
#pragma unroll
    for (int h = 0; h < 8; h++)
#pragma unroll
        for (int o = 16; o; o >>= 1)
            mx[h] = fmaxf(mx[h], __shfl_xor_sync(0xFFFFFFFFu, mx[h], o));

    // pass 2: lane-parallel coefficients, shfl-broadcast accumulation
    float num[8], den[8];
#pragma unroll
    for (int h = 0; h < 8; h++) {
        float e = slf[h] + adv[h];
        e = (e > 0.f) ? e : 0.2f * e;
        float ex = expf(e - mx[h]);
        den[h] = ex;
        num[h] = ex * g_h[d * F + h * 32 + lane];
    }
    for (int base = beg; base < end; base += 32) {
        int m = end - base;
        if (m > 32) m = 32;
        int sown = 0;
        float ex8[8];
        if (lane < m) {
            sown = g_src[base + lane];
            float4 a0 = *(const float4*)&g_as[sown * 8];
            float4 a1 = *(const float4*)&g_as[sown * 8 + 4];
            float av[8] = {a0.x, a0.y, a0.z, a0.w, a1.x, a1.y, a1.z, a1.w};
#pragma unroll
            for (int h = 0; h < 8; h++) {
                float e = av[h] + adv[h];
                e = (e > 0.f) ? e : 0.2f * e;
                ex8[h] = expf(e - mx[h]);
            }
        } else {
#pragma unroll
            for (int h = 0; h < 8; h++) ex8[h] = 0.f;
        }
        for (int j = 0; j < m; j++) {
            int s = __shfl_sync(0xFFFFFFFFu, sown, j);
            const float* hrow = &g_h[(size_t)s * F];
#pragma unroll
            for (int h = 0; h < 8; h++) {
                float coef = __shfl_sync(0xFFFFFFFFu, ex8[h], j);
                den[h] += coef;
                num[h] += coef * hrow[h * 32 + lane];
            }
        }
    }
#pragma unroll
    for (int h = 0; h < 8; h++) {
        float v = num[h] / den[h] + b[h * 32 + lane];
        v = (v > 0.f) ? v : 0.f;
        __nv_bfloat16 hi = __float2bfloat16(v);
        oh[d * F + h * 32 + lane] = hi;
        ol[d * F + h * 32 + lane] = __float2bfloat16(v - __bfloat162float(hi));
    }
}

// ---------------- fused edge head: warp per edge ----------------
__global__ void edge_kernel(const int* __restrict__ ei, const float* __restrict__ ea,
                            const float* __restrict__ Wm1, const float* __restrict__ bm1,
                            const float* __restrict__ Wm2, const float* __restrict__ bm2,
                            const float* __restrict__ Wp1, const float* __restrict__ bp1,
                            const float* __restrict__ Wp2, const float* __restrict__ bp2,
                            float* __restrict__ out) {
    __shared__ float sWm1[1024], sWm2[1024], sWpc[1024];
    __shared__ float sbm1[32], sbm2[32], sbp1[32], sWp2[32];
    for (int t = threadIdx.x; t < 1024; t += blockDim.x) {
        sWm1[t] = Wm1[t];
        sWm2[t] = Wm2[t];
        sWpc[t] = Wp1[512 * 32 + t];
    }
    if (threadIdx.x < 32) {
        sbm1[threadIdx.x] = bm1[threadIdx.x];
        sbm2[threadIdx.x] = bm2[threadIdx.x];
        sbp1[threadIdx.x] = bp1[threadIdx.x];
        sWp2[threadIdx.x] = Wp2[threadIdx.x];
    }
    __syncthreads();

    int w = (blockIdx.x * blockDim.x + threadIdx.x) >> 5;
    int lane = threadIdx.x & 31;
    if (w >= NE) return;

    float eav = ea[w * 32 + lane];

    float a1 = sbm1[lane];
#pragma unroll
    for (int k = 0; k < 32; k++)
        a1 += __shfl_sync(0xFFFFFFFFu, eav, k) * sWm1[k * 32 + lane];
    a1 = fmaxf(a1, 0.f);

    float a2 = sbm2[lane];
#pragma unroll
    for (int k = 0; k < 32; k++)
        a2 += __shfl_sync(0xFFFFFFFFu, a1, k) * sWm2[k * 32 + lane];
    a2 = fmaxf(a2, 0.f);

    float q = 0.f;
#pragma unroll
    for (int k = 0; k < 32; k++)
        q += __shfl_sync(0xFFFFFFFFu, a2, k) * sWpc[k * 32 + lane];

    int r = ei[w], c = ei[NE + w];
    float t = g_P[r * 64 + lane] + g_P[c * 64 + 32 + lane] + q + sbp1[lane];
    t = fmaxf(t, 0.f);

    float s = t * sWp2[lane];
#pragma unroll
    for (int o = 16; o; o >>= 1) s += __shfl_xor_sync(0xFFFFFFFFu, s, o);
    if (lane == 0) out[w] = s + bp2[0];
}

// ---------------- host driver ----------------
extern "C" void kernel_launch(void* const* d_in, const int* in_sizes, int n_in,
                              void* d_out, int out_size) {
    const float* x      = (const float*)d_in[0];
    const int*   ei     = (const int*)  d_in[1];
    const float* ea     = (const float*)d_in[2];
    const float* W1     = (const float*)d_in[3];
    const float* a_src1 = (const float*)d_in[4];
    const float* a_dst1 = (const float*)d_in[5];
    const float* b1     = (const float*)d_in[6];
    const float* W2     = (const float*)d_in[7];
    const float* a_src2 = (const float*)d_in[8];
    const float* a_dst2 = (const float*)d_in[9];
    const float* b2     = (const float*)d_in[10];
    const float* Wm1    = (const float*)d_in[11];
    const float* bm1    = (const float*)d_in[12];
    const float* Wm2    = (const float*)d_in[13];
    const float* bm2    = (const float*)d_in[14];
    const float* Wp1    = (const float*)d_in[15];
    const float* bp1    = (const float*)d_in[16];
    const float* Wp2    = (const float*)d_in[17];
    const float* bp2    = (const float*)d_in[18];
    float* out = (float*)d_out;

    float *gh, *gP;
    __nv_bfloat16 *xh, *xl, *y1h, *y1l, *y2h, *y2l, *w1h, *w1l, *w2h, *w2l, *wch, *wcl;
    cudaGetSymbolAddress((void**)&gh,  g_h);
    cudaGetSymbolAddress((void**)&gP,  g_P);
    cudaGetSymbolAddress((void**)&xh,  g_xh);  cudaGetSymbolAddress((void**)&xl,  g_xl);
    cudaGetSymbolAddress((void**)&y1h, g_y1h); cudaGetSymbolAddress((void**)&y1l, g_y1l);
    cudaGetSymbolAddress((void**)&y2h, g_y2h); cudaGetSymbolAddress((void**)&y2l, g_y2l);
    cudaGetSymbolAddress((void**)&w1h, g_w1h); cudaGetSymbolAddress((void**)&w1l, g_w1l);
    cudaGetSymbolAddress((void**)&w2h, g_w2h); cudaGetSymbolAddress((void**)&w2l, g_w2l);
    cudaGetSymbolAddress((void**)&wch, g_wch); cudaGetSymbolAddress((void**)&wcl, g_wcl);

    // CSR
    csr_zero <<<(NN + 255) / 256, 256>>>();
    csr_count<<<(NE + 255) / 256, 256>>>(ei);
    csr_scan <<<1, 1024>>>();
    csr_fill <<<(NE + 255) / 256, 256>>>(ei);

    // prep: split x, transpose+split weights
    fsplit  <<<(NN * DIN + 255) / 256, 256>>>(x, xh, xl, NN * DIN);
    wprep   <<<(DIN * F + 255) / 256, 256>>>(W1, w1h, w1l, DIN, F);
    wprep   <<<(F * F + 255) / 256, 256>>>(W2, w2h, w2l, F, F);
    wcatprep<<<(64 * F + 255) / 256, 256>>>(Wp1);

    const int MT = (NN + 127) / 128;   // 391

    // layer 1
    gemm_bf16<<<dim3(MT, 4), 256>>>(xh, xl, w1h, w1l, gh, NN, F, DIN);
    alpha_kernel<<<(NN * H * 32 + 255) / 256, 256>>>(a_src1, a_dst1);
    gat_fused<<<(NN * 32 + 255) / 256, 256>>>(b1, y1h, y1l);

    // layer 2
    gemm_bf16<<<dim3(MT, 4), 256>>>(y1h, y1l, w2h, w2l, gh, NN, F, F);
    alpha_kernel<<<(NN * H * 32 + 255) / 256, 256>>>(a_src2, a_dst2);
    gat_fused<<<(NN * 32 + 255) / 256, 256>>>(b2, y2h, y2l);

    // P projection + edge head
    gemm_bf16<<<dim3(MT, 1), 256>>>(y2h, y2l, wch, wcl, gP, NN, 64, F);
    edge_kernel<<<(NE + 7) / 8, 256>>>(ei, ea, Wm1, bm1, Wm2, bm2,
                                       Wp1, bp1, Wp2, bp2, out);
}

// round 12
// speedup vs baseline: 2.6226x; 1.4529x over previous
#include <cuda_runtime.h>
#include <cuda_bf16.h>
#include <math.h>
#include <stdint.h>

#define NN 50000
#define NE 400000
#define DIN 128
#define F 256
#define H 8

// ---------------- scratch (device globals; no allocation) ----------------
__device__ float g_h [NN * F];      // h = x @ W for current layer (fp32)
__device__ float g_as[NN * H];
__device__ float g_ad[NN * H];
__device__ float g_P [NN * 64];     // [Prow(32) | Pcol(32)] per node
// split bf16 activations
__device__ __nv_bfloat16 g_xh[NN * DIN], g_xl[NN * DIN];
__device__ __nv_bfloat16 g_y1h[NN * F],  g_y1l[NN * F];
__device__ __nv_bfloat16 g_y2h[NN * F],  g_y2l[NN * F];
// split+transposed weights [N][K] K-major
__device__ __nv_bfloat16 g_w1h[F * DIN], g_w1l[F * DIN];
__device__ __nv_bfloat16 g_w2h[F * F],   g_w2l[F * F];
__device__ __nv_bfloat16 g_wch[64 * F],  g_wcl[64 * F];
// CSR of incoming real edges
__device__ int g_cnt[NN];
__device__ int g_off[NN + 1];
__device__ int g_cur[NN];
__device__ int g_src[NE];

// ---------------- bf16 mma helpers ----------------
__device__ __forceinline__ void mma_bf16(float* d, const uint32_t* a, const uint32_t* b) {
    asm volatile(
        "mma.sync.aligned.m16n8k16.row.col.f32.bf16.bf16.f32 "
        "{%0,%1,%2,%3}, {%4,%5,%6,%7}, {%8,%9}, {%0,%1,%2,%3};\n"
        : "+f"(d[0]), "+f"(d[1]), "+f"(d[2]), "+f"(d[3])
        : "r"(a[0]), "r"(a[1]), "r"(a[2]), "r"(a[3]), "r"(b[0]), "r"(b[1]));
}
__device__ __forceinline__ uint32_t packbf(float a, float b) {
    __nv_bfloat162 t = __floats2bfloat162_rn(a, b);
    return *(uint32_t*)&t;
}
__device__ __forceinline__ void split2(float a, float b, uint32_t& hi, uint32_t& lo) {
    float ah = __bfloat162float(__float2bfloat16(a));
    float bh = __bfloat162float(__float2bfloat16(b));
    hi = packbf(ah, bh);
    lo = packbf(a - ah, b - bh);
}

// ---------------- split-bf16 tensor GEMM: C[M,Ntot] = A[M,K] @ B^T ----------------
__global__ void __launch_bounds__(256) gemm_bf16(
        const __nv_bfloat16* __restrict__ Ah, const __nv_bfloat16* __restrict__ Al,
        const __nv_bfloat16* __restrict__ Bh, const __nv_bfloat16* __restrict__ Bl,
        float* __restrict__ C, int M, int Ntot, int K) {
    __shared__ __nv_bfloat16 sAh[128 * 40], sAl[128 * 40];
    __shared__ __nv_bfloat16 sBh[64 * 40],  sBl[64 * 40];

    int tid = threadIdx.x;
    int lane = tid & 31, wid = tid >> 5;
    int wm = wid & 3, wn = wid >> 2;
    int g = lane >> 2, tg = lane & 3;
    int rowBase = blockIdx.x * 128;
    int colBase = blockIdx.y * 64;

    float acc[2][4][4];
#pragma unroll
    for (int i = 0; i < 2; i++)
#pragma unroll
        for (int j = 0; j < 4; j++)
#pragma unroll
            for (int q = 0; q < 4; q++) acc[i][j][q] = 0.f;

    const uint32_t* A32h = (const uint32_t*)sAh;
    const uint32_t* A32l = (const uint32_t*)sAl;
    const uint32_t* B32h = (const uint32_t*)sBh;
    const uint32_t* B32l = (const uint32_t*)sBl;

    for (int k0 = 0; k0 < K; k0 += 32) {
#pragma unroll
        for (int l = 0; l < 2; l++) {
            int idx = tid + l * 256;
            int r = idx >> 2, c8 = (idx & 3) << 3;
            uint4 vh = make_uint4(0, 0, 0, 0), vl = make_uint4(0, 0, 0, 0);
            int gr = rowBase + r;
            if (gr < M) {
                vh = *(const uint4*)&Ah[(size_t)gr * K + k0 + c8];
                vl = *(const uint4*)&Al[(size_t)gr * K + k0 + c8];
            }
            *(uint4*)&sAh[r * 40 + c8] = vh;
            *(uint4*)&sAl[r * 40 + c8] = vl;
        }
        {
            int r = tid >> 2, c8 = (tid & 3) << 3;
            int gn = colBase + r;
            uint4 vh = *(const uint4*)&Bh[(size_t)gn * K + k0 + c8];
            uint4 vl = *(const uint4*)&Bl[(size_t)gn * K + k0 + c8];
            *(uint4*)&sBh[r * 40 + c8] = vh;
            *(uint4*)&sBl[r * 40 + c8] = vl;
        }
        __syncthreads();

#pragma unroll
        for (int ks = 0; ks < 2; ks++) {
            int ko = ks << 3;
            uint32_t ah[2][4], al[2][4], bh[4][2], bl[4][2];
#pragma unroll
            for (int i = 0; i < 2; i++) {
                int r = wm * 32 + i * 16 + g;
                ah[i][0] = A32h[r * 20 + ko + tg];
                ah[i][1] = A32h[(r + 8) * 20 + ko + tg];
                ah[i][2] = A32h[r * 20 + ko + 4 + tg];
                ah[i][3] = A32h[(r + 8) * 20 + ko + 4 + tg];
                al[i][0] = A32l[r * 20 + ko + tg];
                al[i][1] = A32l[(r + 8) * 20 + ko + tg];
                al[i][2] = A32l[r * 20 + ko + 4 + tg];
                al[i][3] = A32l[(r + 8) * 20 + ko + 4 + tg];
            }
#pragma unroll
            for (int j = 0; j < 4; j++) {
                int n = wn * 32 + j * 8 + g;
                bh[j][0] = B32h[n * 20 + ko + tg];
                bh[j][1] = B32h[n * 20 + ko + 4 + tg];
                bl[j][0] = B32l[n * 20 + ko + tg];
                bl[j][1] = B32l[n * 20 + ko + 4 + tg];
            }
#pragma unroll
            for (int i = 0; i < 2; i++)
#pragma unroll
                for (int j = 0; j < 4; j++) {
                    mma_bf16(acc[i][j], ah[i], bl[j]);
                    mma_bf16(acc[i][j], al[i], bh[j]);
                    mma_bf16(acc[i][j], ah[i], bh[j]);
                }
        }
        __syncthreads();
    }

#pragma unroll
    for (int i = 0; i < 2; i++) {
        int r = rowBase + wm * 32 + i * 16 + g;
#pragma unroll
        for (int j = 0; j < 4; j++) {
            int c = colBase + wn * 32 + j * 8 + 2 * tg;
            if (r < M)
                *(float2*)&C[(size_t)r * Ntot + c] = make_float2(acc[i][j][0], acc[i][j][1]);
            if (r + 8 < M)
                *(float2*)&C[(size_t)(r + 8) * Ntot + c] = make_float2(acc[i][j][2], acc[i][j][3]);
        }
    }
}

// ---------------- prep kernels ----------------
__global__ void fsplit(const float* __restrict__ s, __nv_bfloat16* __restrict__ h,
                       __nv_bfloat16* __restrict__ l, int n) {
    int i = blockIdx.x * blockDim.x + threadIdx.x;
    if (i >= n) return;
    float v = s[i];
    __nv_bfloat16 hi = __float2bfloat16(v);
    h[i] = hi;
    l[i] = __float2bfloat16(v - __bfloat162float(hi));
}
__global__ void wprep(const float* __restrict__ W, __nv_bfloat16* __restrict__ th,
                      __nv_bfloat16* __restrict__ tl, int K, int N) {
    int i = blockIdx.x * blockDim.x + threadIdx.x;
    if (i >= K * N) return;
    int k = i / N, n = i % N;
    float v = W[i];
    __nv_bfloat16 hi = __float2bfloat16(v);
    th[n * K + k] = hi;
    tl[n * K + k] = __float2bfloat16(v - __bfloat162float(hi));
}
__global__ void wcatprep(const float* __restrict__ Wp1) {
    int i = blockIdx.x * blockDim.x + threadIdx.x;
    if (i >= 64 * 256) return;
    int j = i / 256, k = i % 256;
    float v = (j < 32) ? Wp1[k * 32 + j] : Wp1[(256 + k) * 32 + (j - 32)];
    __nv_bfloat16 hi = __float2bfloat16(v);
    g_wch[i] = hi;
    g_wcl[i] = __float2bfloat16(v - __bfloat162float(hi));
}

// ---------------- CSR build ----------------
__global__ void csr_zero() {
    int i = blockIdx.x * blockDim.x + threadIdx.x;
    if (i < NN) g_cnt[i] = 0;
}
__global__ void csr_count(const int* __restrict__ ei) {
    int e = blockIdx.x * blockDim.x + threadIdx.x;
    if (e < NE) atomicAdd(&g_cnt[ei[NE + e]], 1);
}
__global__ void csr_scan() {
    __shared__ int wsum[32];
    __shared__ int carry_s;
    int t = threadIdx.x, lane = t & 31, wid = t >> 5;
    if (t == 0) carry_s = 0;
    __syncthreads();
    for (int base = 0; base < NN; base += 1024) {
        int i = base + t;
        int v = (i < NN) ? g_cnt[i] : 0;
        int x = v;
#pragma unroll
        for (int o = 1; o < 32; o <<= 1) {
            int y = __shfl_up_sync(0xFFFFFFFFu, x, o);
            if (lane >= o) x += y;
        }
        if (lane == 31) wsum[wid] = x;
        __syncthreads();
        if (wid == 0) {
            int s = wsum[lane];
#pragma unroll
            for (int o = 1; o < 32; o <<= 1) {
                int y = __shfl_up_sync(0xFFFFFFFFu, s, o);
                if (lane >= o) s += y;
            }
            wsum[lane] = s;
        }
        __syncthreads();
        int inc = x + (wid > 0 ? wsum[wid - 1] : 0);
        int exc = carry_s + inc - v;
        if (i < NN) { g_off[i] = exc; g_cur[i] = exc; }
        __syncthreads();
        if (t == 1023) carry_s += wsum[31];
        __syncthreads();
    }
    if (t == 0) g_off[NN] = NE;
}
__global__ void csr_fill(const int* __restrict__ ei) {
    int e = blockIdx.x * blockDim.x + threadIdx.x;
    if (e >= NE) return;
    int d = ei[NE + e];
    int pos = atomicAdd(&g_cur[d], 1);
    g_src[pos] = ei[e];
}

// ---------------- alpha_src/alpha_dst: warp per (node, head) ----------------
__global__ void alpha_kernel(const float* __restrict__ a_src, const float* __restrict__ a_dst) {
    int w = (blockIdx.x * blockDim.x + threadIdx.x) >> 5;
    int lane = threadIdx.x & 31;
    if (w >= NN * H) return;
    int n = w >> 3, hh = w & 7;
    float v = g_h[n * F + hh * 32 + lane];
    float s = v * a_src[hh * 32 + lane];
    float d = v * a_dst[hh * 32 + lane];
#pragma unroll
    for (int o = 16; o; o >>= 1) {
        s += __shfl_xor_sync(0xFFFFFFFFu, s, o);
        d += __shfl_xor_sync(0xFFFFFFFFu, d, o);
    }
    if (lane == 0) { g_as[w] = s; g_ad[w] = d; }
}

// ---------------- fused softmax-attention aggregation: warp per dst ----------------
__global__ void gat_fused(const float* __restrict__ b,
                          __nv_bfloat16* __restrict__ oh, __nv_bfloat16* __restrict__ ol) {
    int w = (blockIdx.x * blockDim.x + threadIdx.x) >> 5;
    int lane = threadIdx.x & 31;
    if (w >= NN) return;
    const int d = w;

    float4 t0 = *(const float4*)&g_ad[d * 8];
    float4 t1 = *(const float4*)&g_ad[d * 8 + 4];
    float adv[8] = {t0.x, t0.y, t0.z, t0.w, t1.x, t1.y, t1.z, t1.w};
    float4 s0 = *(const float4*)&g_as[d * 8];
    float4 s1 = *(const float4*)&g_as[d * 8 + 4];
    float eslf[8];
#pragma unroll
    for (int h = 0; h < 8; h++) {
        float e = ((float*)&s0)[h < 4 ? h : h] * 0.f; // placeholder (overwritten below)
        eslf[h] = 0.f;
    }
    {
        float slf[8] = {s0.x, s0.y, s0.z, s0.w, s1.x, s1.y, s1.z, s1.w};
#pragma unroll
        for (int h = 0; h < 8; h++) {
            float e = slf[h] + adv[h];
            eslf[h] = (e > 0.f) ? e : 0.2f * e;
        }
    }

    int beg = g_off[d], end = g_off[d + 1];
    int cnt = end - beg;

    float num[8], den[8];

    if (cnt <= 32) {
        // single-gather fast path: e values computed once, kept in registers
        int sown = 0;
        float e8[8];
        if (lane < cnt) {
            sown = g_src[beg + lane];
            float4 a0 = *(const float4*)&g_as[sown * 8];
            float4 a1 = *(const float4*)&g_as[sown * 8 + 4];
            float av[8] = {a0.x, a0.y, a0.z, a0.w, a1.x, a1.y, a1.z, a1.w};
#pragma unroll
            for (int h = 0; h < 8; h++) {
                float e = av[h] + adv[h];
                e8[h] = (e > 0.f) ? e : 0.2f * e;
            }
        } else {
#pragma unroll
            for (int h = 0; h < 8; h++) e8[h] = -1e30f;
        }
        float mx[8];
#pragma unroll
        for (int h = 0; h < 8; h++) {
            float m = e8[h];
#pragma unroll
            for (int o = 16; o; o >>= 1)
                m = fmaxf(m, __shfl_xor_sync(0xFFFFFFFFu, m, o));
            mx[h] = fmaxf(m, eslf[h]);
        }
        float ex8[8];
#pragma unroll
        for (int h = 0; h < 8; h++)
            ex8[h] = (lane < cnt) ? expf(e8[h] - mx[h]) : 0.f;
#pragma unroll
        for (int h = 0; h < 8; h++) {
            float exs = expf(eslf[h] - mx[h]);
            den[h] = exs;
            num[h] = exs * g_h[d * F + h * 32 + lane];
        }
        for (int j = 0; j < cnt; j++) {
            int s = __shfl_sync(0xFFFFFFFFu, sown, j);
            const float* hrow = &g_h[(size_t)s * F];
#pragma unroll
            for (int h = 0; h < 8; h++) {
                float coef = __shfl_sync(0xFFFFFFFFu, ex8[h], j);
                den[h] += coef;
                num[h] += coef * hrow[h * 32 + lane];
            }
        }
    } else {
        // two-pass general path
        float mx[8];
#pragma unroll
        for (int h = 0; h < 8; h++) mx[h] = eslf[h];
        for (int i = beg + lane; i < end; i += 32) {
            int s = g_src[i];
            float4 a0 = *(const float4*)&g_as[s * 8];
            float4 a1 = *(const float4*)&g_as[s * 8 + 4];
            float av[8] = {a0.x, a0.y, a0.z, a0.w, a1.x, a1.y, a1.z, a1.w};
#pragma unroll
            for (int h = 0; h < 8; h++) {
                float e = av[h] + adv[h];
                e = (e > 0.f) ? e : 0.2f * e;
                mx[h] = fmaxf(mx[h], e);
            }
        }
#pragma unroll
        for (int h = 0; h < 8; h++)
#pragma unroll
            for (int o = 16; o; o >>= 1)
                mx[h] = fmaxf(mx[h], __shfl_xor_sync(0xFFFFFFFFu, mx[h], o));

#pragma unroll
        for (int h = 0; h < 8; h++) {
            float exs = expf(eslf[h] - mx[h]);
            den[h] = exs;
            num[h] = exs * g_h[d * F + h * 32 + lane];
        }
        for (int base = beg; base < end; base += 32) {
            int m = end - base;
            if (m > 32) m = 32;
            int sown = 0;
            float ex8[8];
            if (lane < m) {
                sown = g_src[base + lane];
                float4 a0 = *(const float4*)&g_as[sown * 8];
                float4 a1 = *(const float4*)&g_as[sown * 8 + 4];
                float av[8] = {a0.x, a0.y, a0.z, a0.w, a1.x, a1.y, a1.z, a1.w};
#pragma unroll
                for (int h = 0; h < 8; h++) {
                    float e = av[h] + adv[h];
                    e = (e > 0.f) ? e : 0.2f * e;
                    ex8[h] = expf(e - mx[h]);
                }
            } else {
#pragma unroll
                for (int h = 0; h < 8; h++) ex8[h] = 0.f;
            }
            for (int j = 0; j < m; j++) {
                int s = __shfl_sync(0xFFFFFFFFu, sown, j);
                const float* hrow = &g_h[(size_t)s * F];
#pragma unroll
                for (int h = 0; h < 8; h++) {
                    float coef = __shfl_sync(0xFFFFFFFFu, ex8[h], j);
                    den[h] += coef;
                    num[h] += coef * hrow[h * 32 + lane];
                }
            }
        }
    }

#pragma unroll
    for (int h = 0; h < 8; h++) {
        float v = num[h] / den[h] + b[h * 32 + lane];
        v = (v > 0.f) ? v : 0.f;
        __nv_bfloat16 hi = __float2bfloat16(v);
        oh[d * F + h * 32 + lane] = hi;
        ol[d * F + h * 32 + lane] = __float2bfloat16(v - __bfloat162float(hi));
    }
}

// ---------------- tensor-core edge head: 128 edges per block, 4 warps ----------------
// q = relu(relu(ea@Wm1+bm1)@Wm2+bm2)@Wpc computed with split-bf16 MMA;
// stage-to-stage conversion is register-local (C frag -> A frag mapping).
// Then out[e] = relu(P[r][ch]+P[c][32+ch]+q[e][ch]+bp1[ch]) . Wp2 + bp2.
__global__ void __launch_bounds__(128) mlp_edge(
        const int* __restrict__ ei, const float* __restrict__ ea,
        const float* __restrict__ Wm1, const float* __restrict__ bm1,
        const float* __restrict__ Wm2, const float* __restrict__ bm2,
        const float* __restrict__ Wp1, const float* __restrict__ bp1,
        const float* __restrict__ Wp2, const float* __restrict__ bp2,
        float* __restrict__ out) {
    // sea (A tiles, hi/lo) overlaid by sq (final q) — sea dead after GEMM1,
    // sq written only after a block-wide sync.
    __shared__ union {
        uint32_t ea32[2][128 * 20];   // [hi/lo][row*20 + kpair]
        float    q[128 * 33];
    } uS;
    __shared__ uint32_t sW[6][32 * 20];   // Wm1h,Wm1l,Wm2h,Wm2l,Wpch,Wpcl as [out][in]
    __shared__ float sb1[32], sb2[32], sbp1[32], sWp2[32];

    int tid = threadIdx.x;
    int lane = tid & 31, wid = tid >> 5;
    int g = lane >> 2, tg = lane & 3;
    int ebase = blockIdx.x * 128;

    // load weights (transpose [in][out] -> [out][in]) + biases
    for (int t = tid; t < 1024; t += 128) {
        int i = t >> 5, o = t & 31;      // in, out
        float v1 = Wm1[i * 32 + o];
        float v2 = Wm2[i * 32 + o];
        float v3 = Wp1[(512 + i) * 32 + o];
        // pack pairs: kpair index i>>1, position i&1
        // write bf16 halves via atomic-free per-element stores into u32 array:
        __nv_bfloat16* w0 = (__nv_bfloat16*)sW[0];
        __nv_bfloat16* w1 = (__nv_bfloat16*)sW[1];
        __nv_bfloat16* w2 = (__nv_bfloat16*)sW[2];
        __nv_bfloat16* w3 = (__nv_bfloat16*)sW[3];
        __nv_bfloat16* w4 = (__nv_bfloat16*)sW[4];
        __nv_bfloat16* w5 = (__nv_bfloat16*)sW[5];
        int idx = o * 40 + i;
        __nv_bfloat16 h1 = __float2bfloat16(v1);
        __nv_bfloat16 h2 = __float2bfloat16(v2);
        __nv_bfloat16 h3 = __float2bfloat16(v3);
        w0[idx] = h1; w1[idx] = __float2bfloat16(v1 - __bfloat162float(h1));
        w2[idx] = h2; w3[idx] = __float2bfloat16(v2 - __bfloat162float(h2));
        w4[idx] = h3; w5[idx] = __float2bfloat16(v3 - __bfloat162float(h3));
    }
    if (tid < 32) {
        sb1[tid] = bm1[tid];
        sb2[tid] = bm2[tid];
        sbp1[tid] = bp1[tid];
        sWp2[tid] = Wp2[tid];
    }

    // load ea rows, split, store to smem (thread = row)
    {
        int e = ebase + tid;
        const float4* src = (const float4*)&ea[(size_t)e * 32];
#pragma unroll
        for (int q4 = 0; q4 < 8; q4++) {
            float4 v = src[q4];
            uint32_t h0, l0, h1, l1;
            split2(v.x, v.y, h0, l0);
            split2(v.z, v.w, h1, l1);
            uS.ea32[0][tid * 20 + q4 * 2]     = h0;
            uS.ea32[0][tid * 20 + q4 * 2 + 1] = h1;
            uS.ea32[1][tid * 20 + q4 * 2]     = l0;
            uS.ea32[1][tid * 20 + q4 * 2 + 1] = l1;
        }
    }
    __syncthreads();

    // ---- GEMM1: A = ea (smem), B = Wm1 ----
    float acc[2][4][4];
#pragma unroll
    for (int i = 0; i < 2; i++)
#pragma unroll
        for (int j = 0; j < 4; j++)
#pragma unroll
            for (int q = 0; q < 4; q++) acc[i][j][q] = 0.f;

    {
        uint32_t bh[4][2][2], bl[4][2][2];   // [j][ks][2]
#pragma unroll
        for (int j = 0; j < 4; j++)
#pragma unroll
            for (int ks = 0; ks < 2; ks++) {
                int n = j * 8 + g, ko = ks * 8;
                bh[j][ks][0] = sW[0][n * 20 + ko + tg];
                bh[j][ks][1] = sW[0][n * 20 + ko + 4 + tg];
                bl[j][ks][0] = sW[1][n * 20 + ko + tg];
                bl[j][ks][1] = sW[1][n * 20 + ko + 4 + tg];
            }
#pragma unroll
        for (int ks = 0; ks < 2; ks++) {
            int ko = ks * 8;
            uint32_t ah[2][4], al[2][4];
#pragma unroll
            for (int i = 0; i < 2; i++) {
                int r = wid * 32 + i * 16 + g;
                ah[i][0] = uS.ea32[0][r * 20 + ko + tg];
                ah[i][1] = uS.ea32[0][(r + 8) * 20 + ko + tg];
                ah[i][2] = uS.ea32[0][r * 20 + ko + 4 + tg];
                ah[i][3] = uS.ea32[0][(r + 8) * 20 + ko + 4 + tg];
                al[i][0] = uS.ea32[1][r * 20 + ko + tg];
                al[i][1] = uS.ea32[1][(r + 8) * 20 + ko + tg];
                al[i][2] = uS.ea32[1][r * 20 + ko + 4 + tg];
                al[i][3] = uS.ea32[1][(r + 8) * 20 + ko + 4 + tg];
            }
#pragma unroll
            for (int i = 0; i < 2; i++)
#pragma unroll
                for (int j = 0; j < 4; j++) {
                    mma_bf16(acc[i][j], ah[i], bl[j][ks]);
                    mma_bf16(acc[i][j], al[i], bh[j][ks]);
                    mma_bf16(acc[i][j], ah[i], bh[j][ks]);
                }
        }
    }

    // ---- stage transition helper (bias+relu+split, register-local), then GEMM ----
#define STAGE(WH, WL, BIAS)                                                       \
    {                                                                             \
        uint32_t ah2[2][2][4], al2[2][2][4];                                      \
        _Pragma("unroll")                                                         \
        for (int i = 0; i < 2; i++)                                               \
            _Pragma("unroll")                                                     \
            for (int ks = 0; ks < 2; ks++) {                                      \
                int j0 = ks * 2, j1 = ks * 2 + 1;                                 \
                float b0 = (BIAS)[j0 * 8 + 2 * tg], b0b = (BIAS)[j0 * 8 + 2 * tg + 1]; \
                float b1 = (BIAS)[j1 * 8 + 2 * tg], b1b = (BIAS)[j1 * 8 + 2 * tg + 1]; \
                float v00 = fmaxf(acc[i][j0][0] + b0, 0.f);                       \
                float v01 = fmaxf(acc[i][j0][1] + b0b, 0.f);                      \
                float v02 = fmaxf(acc[i][j0][2] + b0, 0.f);                       \
                float v03 = fmaxf(acc[i][j0][3] + b0b, 0.f);                      \
                float v10 = fmaxf(acc[i][j1][0] + b1, 0.f);                       \
                float v11 = fmaxf(acc[i][j1][1] + b1b, 0.f);                      \
                float v12 = fmaxf(acc[i][j1][2] + b1, 0.f);                       \
                float v13 = fmaxf(acc[i][j1][3] + b1b, 0.f);                      \
                split2(v00, v01, ah2[i][ks][0], al2[i][ks][0]);                   \
                split2(v02, v03, ah2[i][ks][1], al2[i][ks][1]);                   \
                split2(v10, v11, ah2[i][ks][2], al2[i][ks][2]);                   \
                split2(v12, v13, ah2[i][ks][3], al2[i][ks][3]);                   \
            }                                                                     \
        _Pragma("unroll")                                                         \
        for (int i = 0; i < 2; i++)                                               \
            _Pragma("unroll")                                                     \
            for (int j = 0; j < 4; j++)                                           \
                _Pragma("unroll")                                                 \
                for (int q = 0; q < 4; q++) acc[i][j][q] = 0.f;                   \
        _Pragma("unroll")                                                         \
        for (int ks = 0; ks < 2; ks++) {                                          \
            int ko = ks * 8;                                                      \
            _Pragma("unroll")                                                     \
            for (int j = 0; j < 4; j++) {                                         \
                int n = j * 8 + g;                                                \
                uint32_t wbh[2], wbl[2];                                          \
                wbh[0] = (WH)[n * 20 + ko + tg];                                  \
                wbh[1] = (WH)[n * 20 + ko + 4 + tg];                              \
                wbl[0] = (WL)[n * 20 + ko + tg];                                  \
                wbl[1] = (WL)[n * 20 + ko + 4 + tg];                              \
                _Pragma("unroll")                                                 \
                for (int i = 0; i < 2; i++) {                                     \
                    mma_bf16(acc[i][j], ah2[i][ks], wbl);                         \
                    mma_bf16(acc[i][j], al2[i][ks], wbh);                         \
                    mma_bf16(acc[i][j], ah2[i][ks], wbh);                         \
                }                                                                 \
            }                                                                     \
        }                                                                         \
    }

    STAGE(sW[2], sW[3], sb1)   // GEMM2: relu(GEMM1+bm1) @ Wm2
    STAGE(sW[4], sW[5], sb2)   // GEMM3: relu(GEMM2+bm2) @ Wpc
#undef STAGE

    // ---- write q to smem (after block sync: sea region is dead) ----
    __syncthreads();
#pragma unroll
    for (int i = 0; i < 2; i++) {
        int r = wid * 32 + i * 16 + g;
#pragma unroll
        for (int j = 0; j < 4; j++) {
            int c = j * 8 + 2 * tg;
            uS.q[r * 33 + c]       = acc[i][j][0];
            uS.q[r * 33 + c + 1]   = acc[i][j][1];
            uS.q[(r + 8) * 33 + c]     = acc[i][j][2];
            uS.q[(r + 8) * 33 + c + 1] = acc[i][j][3];
        }
    }
    __syncwarp();

    // ---- finish: warp iterates its 32 edges; lane = channel ----
    int rown = ei[ebase + wid * 32 + lane];
    int coln = ei[NE + ebase + wid * 32 + lane];
    float bpv = sbp1[lane], wp2v = sWp2[lane], bp2v = bp2[0];
    for (int j = 0; j < 32; j++) {
        int r = __shfl_sync(0xFFFFFFFFu, rown, j);
        int c = __shfl_sync(0xFFFFFFFFu, coln, j);
        float t = uS.q[(wid * 32 + j) * 33 + lane]
                + g_P[(size_t)r * 64 + lane] + g_P[(size_t)c * 64 + 32 + lane] + bpv;
        t = fmaxf(t, 0.f);
        float s = t * wp2v;
#pragma unroll
        for (int o = 16; o; o >>= 1) s += __shfl_xor_sync(0xFFFFFFFFu, s, o);
        if (lane == 0) out[ebase + wid * 32 + j] = s + bp2v;
    }
}

// ---------------- host driver ----------------
extern "C" void kernel_launch(void* const* d_in, const int* in_sizes, int n_in,
                              void* d_out, int out_size) {
    const float* x      = (const float*)d_in[0];
    const int*   ei     = (const int*)  d_in[1];
    const float* ea     = (const float*)d_in[2];
    const float* W1     = (const float*)d_in[3];
    const float* a_src1 = (const float*)d_in[4];
    const float* a_dst1 = (const float*)d_in[5];
    const float* b1     = (const float*)d_in[6];
    const float* W2     = (const float*)d_in[7];
    const float* a_src2 = (const float*)d_in[8];
    const float* a_dst2 = (const float*)d_in[9];
    const float* b2     = (const float*)d_in[10];
    const float* Wm1    = (const float*)d_in[11];
    const float* bm1    = (const float*)d_in[12];
    const float* Wm2    = (const float*)d_in[13];
    const float* bm2    = (const float*)d_in[14];
    const float* Wp1    = (const float*)d_in[15];
    const float* bp1    = (const float*)d_in[16];
    const float* Wp2    = (const float*)d_in[17];
    const float* bp2    = (const float*)d_in[18];
    float* out = (float*)d_out;

    float *gh, *gP;
    __nv_bfloat16 *xh, *xl, *y1h, *y1l, *y2h, *y2l, *w1h, *w1l, *w2h, *w2l, *wch, *wcl;
    cudaGetSymbolAddress((void**)&gh,  g_h);
    cudaGetSymbolAddress((void**)&gP,  g_P);
    cudaGetSymbolAddress((void**)&xh,  g_xh);  cudaGetSymbolAddress((void**)&xl,  g_xl);
    cudaGetSymbolAddress((void**)&y1h, g_y1h); cudaGetSymbolAddress((void**)&y1l, g_y1l);
    cudaGetSymbolAddress((void**)&y2h, g_y2h); cudaGetSymbolAddress((void**)&y2l, g_y2l);
    cudaGetSymbolAddress((void**)&w1h, g_w1h); cudaGetSymbolAddress((void**)&w1l, g_w1l);
    cudaGetSymbolAddress((void**)&w2h, g_w2h); cudaGetSymbolAddress((void**)&w2l, g_w2l);
    cudaGetSymbolAddress((void**)&wch, g_wch); cudaGetSymbolAddress((void**)&wcl, g_wcl);

    const int MT = (NN + 127) / 128;   // 391

    // prep first (puts gemm_bf16 at launch slot 4 for the profiler)
    fsplit  <<<(NN * DIN + 255) / 256, 256>>>(x, xh, xl, NN * DIN);
    wprep   <<<(DIN * F + 255) / 256, 256>>>(W1, w1h, w1l, DIN, F);
    wprep   <<<(F * F + 255) / 256, 256>>>(W2, w2h, w2l, F, F);

    // layer-1 GEMM (4th launch)
    gemm_bf16<<<dim3(MT, 4), 256>>>(xh, xl, w1h, w1l, gh, NN, F, DIN);

    wcatprep<<<(64 * F + 255) / 256, 256>>>(Wp1);

    // CSR (needed before gat_fused)
    csr_zero <<<(NN + 255) / 256, 256>>>();
    csr_count<<<(NE + 255) / 256, 256>>>(ei);
    csr_scan <<<1, 1024>>>();
    csr_fill <<<(NE + 255) / 256, 256>>>(ei);

    // layer 1 attention
    alpha_kernel<<<(NN * H * 32 + 255) / 256, 256>>>(a_src1, a_dst1);
    gat_fused<<<(NN * 32 + 255) / 256, 256>>>(b1, y1h, y1l);

    // layer 2
    gemm_bf16<<<dim3(MT, 4), 256>>>(y1h, y1l, w2h, w2l, gh, NN, F, F);
    alpha_kernel<<<(NN * H * 32 + 255) / 256, 256>>>(a_src2, a_dst2);
    gat_fused<<<(NN * 32 + 255) / 256, 256>>>(b2, y2h, y2l);

    // P projection + tensor edge head
    gemm_bf16<<<dim3(MT, 1), 256>>>(y2h, y2l, wch, wcl, gP, NN, 64, F);
    mlp_edge<<<NE / 128, 128>>>(ei, ea, Wm1, bm1, Wm2, bm2,
                                Wp1, bp1, Wp2, bp2, out);
}

// round 14
// speedup vs baseline: 2.7337x; 1.0423x over previous
#include <cuda_runtime.h>
#include <cuda_bf16.h>
#include <math.h>
#include <stdint.h>

#define NN 50000
#define NE 400000
#define DIN 128
#define F 256
#define H 8

// ---------------- scratch (device globals; no allocation) ----------------
__device__ float g_h [NN * F];      // h = x @ W for current layer (fp32)
__device__ float g_as[NN * H];
__device__ float g_ad[NN * H];
__device__ float g_P [NN * 64];     // [Prow(32) | Pcol(32)] per node
// split bf16 activations
__device__ __nv_bfloat16 g_xh[NN * DIN], g_xl[NN * DIN];
__device__ __nv_bfloat16 g_y1h[NN * F],  g_y1l[NN * F];
__device__ __nv_bfloat16 g_y2h[NN * F],  g_y2l[NN * F];
// split+transposed weights [N][K] K-major
__device__ __nv_bfloat16 g_w1h[F * DIN], g_w1l[F * DIN];
__device__ __nv_bfloat16 g_w2h[F * F],   g_w2l[F * F];
__device__ __nv_bfloat16 g_wch[64 * F],  g_wcl[64 * F];
// CSR of incoming real edges
__device__ int g_cnt[NN];
__device__ int g_off[NN + 1];
__device__ int g_cur[NN];
__device__ int g_src[NE];

// ---------------- helpers ----------------
__device__ __forceinline__ uint32_t smem_u32(const void* p) {
    uint32_t a;
    asm("{ .reg .u64 t; cvta.to.shared.u64 t, %1; cvt.u32.u64 %0, t; }" : "=r"(a) : "l"(p));
    return a;
}
__device__ __forceinline__ void mma_bf16(float* d, const uint32_t* a, const uint32_t* b) {
    asm volatile(
        "mma.sync.aligned.m16n8k16.row.col.f32.bf16.bf16.f32 "
        "{%0,%1,%2,%3}, {%4,%5,%6,%7}, {%8,%9}, {%0,%1,%2,%3};\n"
        : "+f"(d[0]), "+f"(d[1]), "+f"(d[2]), "+f"(d[3])
        : "r"(a[0]), "r"(a[1]), "r"(a[2]), "r"(a[3]), "r"(b[0]), "r"(b[1]));
}
__device__ __forceinline__ uint32_t packbf(float a, float b) {
    __nv_bfloat162 t = __floats2bfloat162_rn(a, b);
    return *(uint32_t*)&t;
}
__device__ __forceinline__ void split2(float a, float b, uint32_t& hi, uint32_t& lo) {
    float ah = __bfloat162float(__float2bfloat16(a));
    float bh = __bfloat162float(__float2bfloat16(b));
    hi = packbf(ah, bh);
    lo = packbf(a - ah, b - bh);
}
__device__ __forceinline__ void ldsm4(uint32_t* r, uint32_t addr) {
    asm volatile("ldmatrix.sync.aligned.m8n8.x4.shared.b16 {%0,%1,%2,%3}, [%4];"
        : "=r"(r[0]), "=r"(r[1]), "=r"(r[2]), "=r"(r[3]) : "r"(addr));
}
__device__ __forceinline__ void ldsm2(uint32_t* r, uint32_t addr) {
    asm volatile("ldmatrix.sync.aligned.m8n8.x2.shared.b16 {%0,%1}, [%2];"
        : "=r"(r[0]), "=r"(r[1]) : "r"(addr));
}
__device__ __forceinline__ void cpa16(uint32_t dst, const void* src, int sz) {
    asm volatile("cp.async.cg.shared.global [%0], [%1], 16, %2;"
        :: "r"(dst), "l"(src), "r"(sz));
}
#define CPA_COMMIT() asm volatile("cp.async.commit_group;")
#define CPA_WAIT(n)  asm volatile("cp.async.wait_group %0;" :: "n"(n))

// ---------------- split-bf16 tensor GEMM: C[M,Ntot] = A[M,K] @ B^T ----------------
// Block tile 128x64, BK=32, cp.async double-buffered, ldmatrix fragment loads.
// smem rows stride 40 bf16 (80B) -> ldmatrix phases conflict-free.
#define ASZB (128 * 40 * 2)
#define BSZB (64 * 40 * 2)
#define GEMM_SMEM (4 * ASZB + 4 * BSZB)   // 61440

__global__ void __launch_bounds__(256) gemm_bf16(
        const __nv_bfloat16* __restrict__ Ah, const __nv_bfloat16* __restrict__ Al,
        const __nv_bfloat16* __restrict__ Bh, const __nv_bfloat16* __restrict__ Bl,
        float* __restrict__ C, int M, int Ntot, int K) {
    extern __shared__ char dynsmem[];
    const uint32_t sb = smem_u32(dynsmem);
    const uint32_t OAH = 0, OAL = 2 * ASZB, OBH = 4 * ASZB, OBL = 4 * ASZB + 2 * BSZB;

    int tid = threadIdx.x;
    int lane = tid & 31, wid = tid >> 5;
    int wm = wid & 3, wn = wid >> 2;
    int g = lane >> 2, tg = lane & 3;
    int rowBase = blockIdx.x * 128;
    int colBase = blockIdx.y * 64;

    // per-thread load coordinates
    int ar0 = tid >> 2, ac8_0 = (tid & 3) << 3;            // A chunk 1 (rows 0..63)
    int ar1 = (tid + 256) >> 2, ac8_1 = ac8_0;             // A chunk 2 (rows 64..127)
    int br = tid >> 2, bc8 = (tid & 3) << 3;               // B rows 0..63

    float acc[2][4][4];
#pragma unroll
    for (int i = 0; i < 2; i++)
#pragma unroll
        for (int j = 0; j < 4; j++)
#pragma unroll
            for (int q = 0; q < 4; q++) acc[i][j][q] = 0.f;

    int nch = K >> 5;

    // ---- async load of one stage ----
    auto load_stage = [&](int stage, int k0) {
        uint32_t stA = sb + stage * ASZB;
        uint32_t stB = sb + stage * BSZB;
        {
            int gr = rowBase + ar0;
            int sz = (gr < M) ? 16 : 0;
            int grc = (gr < M) ? gr : (M - 1);
            size_t off = (size_t)grc * K + k0 + ac8_0;
            uint32_t d = stA + (ar0 * 40 + ac8_0) * 2;
            cpa16(d + OAH, Ah + off, sz);
            cpa16(d + OAL, Al + off, sz);
        }
        {
            int gr = rowBase + ar1;
            int sz = (gr < M) ? 16 : 0;
            int grc = (gr < M) ? gr : (M - 1);
            size_t off = (size_t)grc * K + k0 + ac8_1;
            uint32_t d = stA + (ar1 * 40 + ac8_1) * 2;
            cpa16(d + OAH, Ah + off, sz);
            cpa16(d + OAL, Al + off, sz);
        }
        {
            size_t off = (size_t)(colBase + br) * K + k0 + bc8;
            uint32_t d = stB + (br * 40 + bc8) * 2;
            cpa16(d + OBH, Bh + off, 16);
            cpa16(d + OBL, Bl + off, 16);
        }
        CPA_COMMIT();
    };

    load_stage(0, 0);

    for (int ch = 0; ch < nch; ch++) {
        if (ch + 1 < nch) {
            load_stage((ch + 1) & 1, (ch + 1) << 5);
            CPA_WAIT(1);
        } else {
            CPA_WAIT(0);
        }
        __syncthreads();

        int stage = ch & 1;
        uint32_t aH = sb + OAH + stage * ASZB;
        uint32_t aL = sb + OAL + stage * ASZB;
        uint32_t bH = sb + OBH + stage * BSZB;
        uint32_t bL = sb + OBL + stage * BSZB;

        int l16 = lane & 15;
        // A ldmatrix address pattern: row = base + (lane%16), col8 = (lane/16)*8
        int arow = (lane & 15), ak8 = (lane >> 4) << 3;
        // B ldmatrix (x2): row = n0 + (l16%8), col8 = (l16/8)*8
        int brow = l16 & 7, bk8 = (l16 >> 3) << 3;

#pragma unroll
        for (int ks = 0; ks < 2; ks++) {
            uint32_t ah[2][4], al[2][4], bh[4][2], bl[4][2];
#pragma unroll
            for (int i = 0; i < 2; i++) {
                int r = wm * 32 + i * 16 + arow;
                uint32_t o = (uint32_t)(r * 40 + ks * 16 + ak8) * 2;
                ldsm4(ah[i], aH + o);
                ldsm4(al[i], aL + o);
            }
#pragma unroll
            for (int j = 0; j < 4; j++) {
                int n = wn * 32 + j * 8 + brow;
                uint32_t o = (uint32_t)(n * 40 + ks * 16 + bk8) * 2;
                ldsm2(bh[j], bH + o);
                ldsm2(bl[j], bL + o);
            }
#pragma unroll
            for (int i = 0; i < 2; i++)
#pragma unroll
                for (int j = 0; j < 4; j++) {
                    mma_bf16(acc[i][j], ah[i], bl[j]);
                    mma_bf16(acc[i][j], al[i], bh[j]);
                    mma_bf16(acc[i][j], ah[i], bh[j]);
                }
        }
        __syncthreads();
    }

#pragma unroll
    for (int i = 0; i < 2; i++) {
        int r = rowBase + wm * 32 + i * 16 + g;
#pragma unroll
        for (int j = 0; j < 4; j++) {
            int c = colBase + wn * 32 + j * 8 + 2 * tg;
            if (r < M)
                *(float2*)&C[(size_t)r * Ntot + c] = make_float2(acc[i][j][0], acc[i][j][1]);
            if (r + 8 < M)
                *(float2*)&C[(size_t)(r + 8) * Ntot + c] = make_float2(acc[i][j][2], acc[i][j][3]);
        }
    }
}

// ---------------- prep kernels ----------------
__global__ void fsplit(const float* __restrict__ s, __nv_bfloat16* __restrict__ h,
                       __nv_bfloat16* __restrict__ l, int n) {
    int i = blockIdx.x * blockDim.x + threadIdx.x;
    if (i >= n) return;
    float v = s[i];
    __nv_bfloat16 hi = __float2bfloat16(v);
    h[i] = hi;
    l[i] = __float2bfloat16(v - __bfloat162float(hi));
}
__global__ void wprep(const float* __restrict__ W, __nv_bfloat16* __restrict__ th,
                      __nv_bfloat16* __restrict__ tl, int K, int N) {
    int i = blockIdx.x * blockDim.x + threadIdx.x;
    if (i >= K * N) return;
    int k = i / N, n = i % N;
    float v = W[i];
    __nv_bfloat16 hi = __float2bfloat16(v);
    th[n * K + k] = hi;
    tl[n * K + k] = __float2bfloat16(v - __bfloat162float(hi));
}
__global__ void wcatprep(const float* __restrict__ Wp1) {
    int i = blockIdx.x * blockDim.x + threadIdx.x;
    if (i >= 64 * 256) return;
    int j = i / 256, k = i % 256;
    float v = (j < 32) ? Wp1[k * 32 + j] : Wp1[(256 + k) * 32 + (j - 32)];
    __nv_bfloat16 hi = __float2bfloat16(v);
    g_wch[i] = hi;
    g_wcl[i] = __float2bfloat16(v - __bfloat162float(hi));
}

// ---------------- CSR build ----------------
__global__ void csr_zero() {
    int i = blockIdx.x * blockDim.x + threadIdx.x;
    if (i < NN) g_cnt[i] = 0;
}
__global__ void csr_count(const int* __restrict__ ei) {
    int e = blockIdx.x * blockDim.x + threadIdx.x;
    if (e < NE) atomicAdd(&g_cnt[ei[NE + e]], 1);
}
__global__ void csr_scan() {
    __shared__ int wsum[32];
    __shared__ int carry_s;
    int t = threadIdx.x, lane = t & 31, wid = t >> 5;
    if (t == 0) carry_s = 0;
    __syncthreads();
    for (int base = 0; base < NN; base += 1024) {
        int i = base + t;
        int v = (i < NN) ? g_cnt[i] : 0;
        int x = v;
#pragma unroll
        for (int o = 1; o < 32; o <<= 1) {
            int y = __shfl_up_sync(0xFFFFFFFFu, x, o);
            if (lane >= o) x += y;
        }
        if (lane == 31) wsum[wid] = x;
        __syncthreads();
        if (wid == 0) {
            int s = wsum[lane];
#pragma unroll
            for (int o = 1; o < 32; o <<= 1) {
                int y = __shfl_up_sync(0xFFFFFFFFu, s, o);
                if (lane >= o) s += y;
            }
            wsum[lane] = s;
        }
        __syncthreads();
        int inc = x + (wid > 0 ? wsum[wid - 1] : 0);
        int exc = carry_s + inc - v;
        if (i < NN) { g_off[i] = exc; g_cur[i] = exc; }
        __syncthreads();
        if (t == 1023) carry_s += wsum[31];
        __syncthreads();
    }
    if (t == 0) g_off[NN] = NE;
}
__global__ void csr_fill(const int* __restrict__ ei) {
    int e = blockIdx.x * blockDim.x + threadIdx.x;
    if (e >= NE) return;
    int d = ei[NE + e];
    int pos = atomicAdd(&g_cur[d], 1);
    g_src[pos] = ei[e];
}

// ---------------- alpha_src/alpha_dst: warp per (node, head) ----------------
__global__ void alpha_kernel(const float* __restrict__ a_src, const float* __restrict__ a_dst) {
    int w = (blockIdx.x * blockDim.x + threadIdx.x) >> 5;
    int lane = threadIdx.x & 31;
    if (w >= NN * H) return;
    int n = w >> 3, hh = w & 7;
    float v = g_h[n * F + hh * 32 + lane];
    float s = v * a_src[hh * 32 + lane];
    float d = v * a_dst[hh * 32 + lane];
#pragma unroll
    for (int o = 16; o; o >>= 1) {
        s += __shfl_xor_sync(0xFFFFFFFFu, s, o);
        d += __shfl_xor_sync(0xFFFFFFFFu, d, o);
    }
    if (lane == 0) { g_as[w] = s; g_ad[w] = d; }
}

// ---------------- fused softmax-attention aggregation: warp per dst ----------------
__global__ void gat_fused(const float* __restrict__ b,
                          __nv_bfloat16* __restrict__ oh, __nv_bfloat16* __restrict__ ol) {
    int w = (blockIdx.x * blockDim.x + threadIdx.x) >> 5;
    int lane = threadIdx.x & 31;
    if (w >= NN) return;
    const int d = w;

    float4 t0 = *(const float4*)&g_ad[d * 8];
    float4 t1 = *(const float4*)&g_ad[d * 8 + 4];
    float adv[8] = {t0.x, t0.y, t0.z, t0.w, t1.x, t1.y, t1.z, t1.w};
    float4 s0 = *(const float4*)&g_as[d * 8];
    float4 s1 = *(const float4*)&g_as[d * 8 + 4];
    float eslf[8];
    {
        float slf[8] = {s0.x, s0.y, s0.z, s0.w, s1.x, s1.y, s1.z, s1.w};
#pragma unroll
        for (int h = 0; h < 8; h++) {
            float e = slf[h] + adv[h];
            eslf[h] = (e > 0.f) ? e : 0.2f * e;
        }
    }

    int beg = g_off[d], end = g_off[d + 1];
    int cnt = end - beg;

    float num[8], den[8];

    if (cnt <= 32) {
        int sown = 0;
        float e8[8];
        if (lane < cnt) {
            sown = g_src[beg + lane];
            float4 a0 = *(const float4*)&g_as[sown * 8];
            float4 a1 = *(const float4*)&g_as[sown * 8 + 4];
            float av[8] = {a0.x, a0.y, a0.z, a0.w, a1.x, a1.y, a1.z, a1.w};
#pragma unroll
            for (int h = 0; h < 8; h++) {
                float e = av[h] + adv[h];
                e8[h] = (e > 0.f) ? e : 0.2f * e;
            }
        } else {
#pragma unroll
            for (int h = 0; h < 8; h++) e8[h] = -1e30f;
        }
        float mx[8];
#pragma unroll
        for (int h = 0; h < 8; h++) {
            float m = e8[h];
#pragma unroll
            for (int o = 16; o; o >>= 1)
                m = fmaxf(m, __shfl_xor_sync(0xFFFFFFFFu, m, o));
            mx[h] = fmaxf(m, eslf[h]);
        }
        float ex8[8];
#pragma unroll
        for (int h = 0; h < 8; h++)
            ex8[h] = (lane < cnt) ? expf(e8[h] - mx[h]) : 0.f;
#pragma unroll
        for (int h = 0; h < 8; h++) {
            float exs = expf(eslf[h] - mx[h]);
            den[h] = exs;
            num[h] = exs * g_h[d * F + h * 32 + lane];
        }
        for (int j = 0; j < cnt; j++) {
            int s = __shfl_sync(0xFFFFFFFFu, sown, j);
            const float* hrow = &g_h[(size_t)s * F];
#pragma unroll
            for (int h = 0; h < 8; h++) {
                float coef = __shfl_sync(0xFFFFFFFFu, ex8[h], j);
                den[h] += coef;
                num[h] += coef * hrow[h * 32 + lane];
            }
        }
    } else {
        float mx[8];
#pragma unroll
        for (int h = 0; h < 8; h++) mx[h] = eslf[h];
        for (int i = beg + lane; i < end; i += 32) {
            int s = g_src[i];
            float4 a0 = *(const float4*)&g_as[s * 8];
            float4 a1 = *(const float4*)&g_as[s * 8 + 4];
            float av[8] = {a0.x, a0.y, a0.z, a0.w, a1.x, a1.y, a1.z, a1.w};
#pragma unroll
            for (int h = 0; h < 8; h++) {
                float e = av[h] + adv[h];
                e = (e > 0.f) ? e : 0.2f * e;
                mx[h] = fmaxf(mx[h], e);
            }
        }
#pragma unroll
        for (int h = 0; h < 8; h++)
#pragma unroll
            for (int o = 16; o; o >>= 1)
                mx[h] = fmaxf(mx[h], __shfl_xor_sync(0xFFFFFFFFu, mx[h], o));

#pragma unroll
        for (int h = 0; h < 8; h++) {
            float exs = expf(eslf[h] - mx[h]);
            den[h] = exs;
            num[h] = exs * g_h[d * F + h * 32 + lane];
        }
        for (int base = beg; base < end; base += 32) {
            int m = end - base;
            if (m > 32) m = 32;
            int sown = 0;
            float ex8[8];
            if (lane < m) {
                sown = g_src[base + lane];
                float4 a0 = *(const float4*)&g_as[sown * 8];
                float4 a1 = *(const float4*)&g_as[sown * 8 + 4];
                float av[8] = {a0.x, a0.y, a0.z, a0.w, a1.x, a1.y, a1.z, a1.w};
#pragma unroll
                for (int h = 0; h < 8; h++) {
                    float e = av[h] + adv[h];
                    e = (e > 0.f) ? e : 0.2f * e;
                    ex8[h] = expf(e - mx[h]);
                }
            } else {
#pragma unroll
                for (int h = 0; h < 8; h++) ex8[h] = 0.f;
            }
            for (int j = 0; j < m; j++) {
                int s = __shfl_sync(0xFFFFFFFFu, sown, j);
                const float* hrow = &g_h[(size_t)s * F];
#pragma unroll
                for (int h = 0; h < 8; h++) {
                    float coef = __shfl_sync(0xFFFFFFFFu, ex8[h], j);
                    den[h] += coef;
                    num[h] += coef * hrow[h * 32 + lane];
                }
            }
        }
    }

#pragma unroll
    for (int h = 0; h < 8; h++) {
        float v = num[h] / den[h] + b[h * 32 + lane];
        v = (v > 0.f) ? v : 0.f;
        __nv_bfloat16 hi = __float2bfloat16(v);
        oh[d * F + h * 32 + lane] = hi;
        ol[d * F + h * 32 + lane] = __float2bfloat16(v - __bfloat162float(hi));
    }
}

// ---------------- tensor-core edge head: 128 edges per block, 4 warps ----------------
__global__ void __launch_bounds__(128) mlp_edge(
        const int* __restrict__ ei, const float* __restrict__ ea,
        const float* __restrict__ Wm1, const float* __restrict__ bm1,
        const float* __restrict__ Wm2, const float* __restrict__ bm2,
        const float* __restrict__ Wp1, const float* __restrict__ bp1,
        const float* __restrict__ Wp2, const float* __restrict__ bp2,
        float* __restrict__ out) {
    __shared__ union {
        uint32_t ea32[2][128 * 20];
        float    q[128 * 33];
    } uS;
    __shared__ uint32_t sW[6][32 * 20];
    __shared__ float sb1[32], sb2[32], sbp1[32], sWp2[32];

    int tid = threadIdx.x;
    int lane = tid & 31, wid = tid >> 5;
    int g = lane >> 2, tg = lane & 3;
    int ebase = blockIdx.x * 128;

    for (int t = tid; t < 1024; t += 128) {
        int i = t >> 5, o = t & 31;
        float v1 = Wm1[i * 32 + o];
        float v2 = Wm2[i * 32 + o];
        float v3 = Wp1[(512 + i) * 32 + o];
        __nv_bfloat16* w0 = (__nv_bfloat16*)sW[0];
        __nv_bfloat16* w1 = (__nv_bfloat16*)sW[1];
        __nv_bfloat16* w2 = (__nv_bfloat16*)sW[2];
        __nv_bfloat16* w3 = (__nv_bfloat16*)sW[3];
        __nv_bfloat16* w4 = (__nv_bfloat16*)sW[4];
        __nv_bfloat16* w5 = (__nv_bfloat16*)sW[5];
        int idx = o * 40 + i;
        __nv_bfloat16 h1 = __float2bfloat16(v1);
        __nv_bfloat16 h2 = __float2bfloat16(v2);
        __nv_bfloat16 h3 = __float2bfloat16(v3);
        w0[idx] = h1; w1[idx] = __float2bfloat16(v1 - __bfloat162float(h1));
        w2[idx] = h2; w3[idx] = __float2bfloat16(v2 - __bfloat162float(h2));
        w4[idx] = h3; w5[idx] = __float2bfloat16(v3 - __bfloat162float(h3));
    }
    if (tid < 32) {
        sb1[tid] = bm1[tid];
        sb2[tid] = bm2[tid];
        sbp1[tid] = bp1[tid];
        sWp2[tid] = Wp2[tid];
    }

    {
        int e = ebase + tid;
        const float4* src = (const float4*)&ea[(size_t)e * 32];
#pragma unroll
        for (int q4 = 0; q4 < 8; q4++) {
            float4 v = src[q4];
            uint32_t h0, l0, h1, l1;
            split2(v.x, v.y, h0, l0);
            split2(v.z, v.w, h1, l1);
            uS.ea32[0][tid * 20 + q4 * 2]     = h0;
            uS.ea32[0][tid * 20 + q4 * 2 + 1] = h1;
            uS.ea32[1][tid * 20 + q4 * 2]     = l0;
            uS.ea32[1][tid * 20 + q4 * 2 + 1] = l1;
        }
    }
    __syncthreads();

    float acc[2][4][4];
#pragma unroll
    for (int i = 0; i < 2; i++)
#pragma unroll
        for (int j = 0; j < 4; j++)
#pragma unroll
            for (int q = 0; q < 4; q++) acc[i][j][q] = 0.f;

    {
        uint32_t bh[4][2][2], bl[4][2][2];
#pragma unroll
        for (int j = 0; j < 4; j++)
#pragma unroll
            for (int ks = 0; ks < 2; ks++) {
                int n = j * 8 + g, ko = ks * 8;
                bh[j][ks][0] = sW[0][n * 20 + ko + tg];
                bh[j][ks][1] = sW[0][n * 20 + ko + 4 + tg];
                bl[j][ks][0] = sW[1][n * 20 + ko + tg];
                bl[j][ks][1] = sW[1][n * 20 + ko + 4 + tg];
            }
#pragma unroll
        for (int ks = 0; ks < 2; ks++) {
            int ko = ks * 8;
            uint32_t ah[2][4], al[2][4];
#pragma unroll
            for (int i = 0; i < 2; i++) {
                int r = wid * 32 + i * 16 + g;
                ah[i][0] = uS.ea32[0][r * 20 + ko + tg];
                ah[i][1] = uS.ea32[0][(r + 8) * 20 + ko + tg];
                ah[i][2] = uS.ea32[0][r * 20 + ko + 4 + tg];
                ah[i][3] = uS.ea32[0][(r + 8) * 20 + ko + 4 + tg];
                al[i][0] = uS.ea32[1][r * 20 + ko + tg];
                al[i][1] = uS.ea32[1][(r + 8) * 20 + ko + tg];
                al[i][2] = uS.ea32[1][r * 20 + ko + 4 + tg];
                al[i][3] = uS.ea32[1][(r + 8) * 20 + ko + 4 + tg];
            }
#pragma unroll
            for (int i = 0; i < 2; i++)
#pragma unroll
                for (int j = 0; j < 4; j++) {
                    mma_bf16(acc[i][j], ah[i], bl[j][ks]);
                    mma_bf16(acc[i][j], al[i], bh[j][ks]);
                    mma_bf16(acc[i][j], ah[i], bh[j][ks]);
                }
        }
    }

#define STAGE(WH, WL, BIAS)                                                       \
    {                                                                             \
        uint32_t ah2[2][2][4], al2[2][2][4];                                      \
        _Pragma("unroll")                                                         \
        for (int i = 0; i < 2; i++)                                               \
            _Pragma("unroll")                                                     \
            for (int ks = 0; ks < 2; ks++) {                                      \
                int j0 = ks * 2, j1 = ks * 2 + 1;                                 \
                float b0 = (BIAS)[j0 * 8 + 2 * tg], b0b = (BIAS)[j0 * 8 + 2 * tg + 1]; \
                float b1 = (BIAS)[j1 * 8 + 2 * tg], b1b = (BIAS)[j1 * 8 + 2 * tg + 1]; \
                float v00 = fmaxf(acc[i][j0][0] + b0, 0.f);                       \
                float v01 = fmaxf(acc[i][j0][1] + b0b, 0.f);                      \
                float v02 = fmaxf(acc[i][j0][2] + b0, 0.f);                       \
                float v03 = fmaxf(acc[i][j0][3] + b0b, 0.f);                      \
                float v10 = fmaxf(acc[i][j1][0] + b1, 0.f);                       \
                float v11 = fmaxf(acc[i][j1][1] + b1b, 0.f);                      \
                float v12 = fmaxf(acc[i][j1][2] + b1, 0.f);                       \
                float v13 = fmaxf(acc[i][j1][3] + b1b, 0.f);                      \
                split2(v00, v01, ah2[i][ks][0], al2[i][ks][0]);                   \
                split2(v02, v03, ah2[i][ks][1], al2[i][ks][1]);                   \
                split2(v10, v11, ah2[i][ks][2], al2[i][ks][2]);                   \
                split2(v12, v13, ah2[i][ks][3], al2[i][ks][3]);                   \
            }                                                                     \
        _Pragma("unroll")                                                         \
        for (int i = 0; i < 2; i++)                                               \
            _Pragma("unroll")                                                     \
            for (int j = 0; j < 4; j++)                                           \
                _Pragma("unroll")                                                 \
                for (int q = 0; q < 4; q++) acc[i][j][q] = 0.f;                   \
        _Pragma("unroll")                                                         \
        for (int ks = 0; ks < 2; ks++) {                                          \
            int ko = ks * 8;                                                      \
            _Pragma("unroll")                                                     \
            for (int j = 0; j < 4; j++) {                                         \
                int n = j * 8 + g;                                                \
                uint32_t wbh[2], wbl[2];                                          \
                wbh[0] = (WH)[n * 20 + ko + tg];                                  \
                wbh[1] = (WH)[n * 20 + ko + 4 + tg];                              \
                wbl[0] = (WL)[n * 20 + ko + tg];                                  \
                wbl[1] = (WL)[n * 20 + ko + 4 + tg];                              \
                _Pragma("unroll")                                                 \
                for (int i = 0; i < 2; i++) {                                     \
                    mma_bf16(acc[i][j], ah2[i][ks], wbl);                         \
                    mma_bf16(acc[i][j], al2[i][ks], wbh);                         \
                    mma_bf16(acc[i][j], ah2[i][ks], wbh);                         \
                }                                                                 \
            }                                                                     \
        }                                                                         \
    }

    STAGE(sW[2], sW[3], sb1)
    STAGE(sW[4], sW[5], sb2)
#undef STAGE

    __syncthreads();
#pragma unroll
    for (int i = 0; i < 2; i++) {
        int r = wid * 32 + i * 16 + g;
#pragma unroll
        for (int j = 0; j < 4; j++) {
            int c = j * 8 + 2 * tg;
            uS.q[r * 33 + c]       = acc[i][j][0];
            uS.q[r * 33 + c + 1]   = acc[i][j][1];
            uS.q[(r + 8) * 33 + c]     = acc[i][j][2];
            uS.q[(r + 8) * 33 + c + 1] = acc[i][j][3];
        }
    }
    __syncwarp();

    int rown = ei[ebase + wid * 32 + lane];
    int coln = ei[NE + ebase + wid * 32 + lane];
    float bpv = sbp1[lane], wp2v = sWp2[lane], bp2v = bp2[0];
    for (int j = 0; j < 32; j++) {
        int r = __shfl_sync(0xFFFFFFFFu, rown, j);
        int c = __shfl_sync(0xFFFFFFFFu, coln, j);
        float t = uS.q[(wid * 32 + j) * 33 + lane]
                + g_P[(size_t)r * 64 + lane] + g_P[(size_t)c * 64 + 32 + lane] + bpv;
        t = fmaxf(t, 0.f);
        float s = t * wp2v;
#pragma unroll
        for (int o = 16; o; o >>= 1) s += __shfl_xor_sync(0xFFFFFFFFu, s, o);
        if (lane == 0) out[ebase + wid * 32 + j] = s + bp2v;
    }
}

// ---------------- host driver ----------------
extern "C" void kernel_launch(void* const* d_in, const int* in_sizes, int n_in,
                              void* d_out, int out_size) {
    const float* x      = (const float*)d_in[0];
    const int*   ei     = (const int*)  d_in[1];
    const float* ea     = (const float*)d_in[2];
    const float* W1     = (const float*)d_in[3];
    const float* a_src1 = (const float*)d_in[4];
    const float* a_dst1 = (const float*)d_in[5];
    const float* b1     = (const float*)d_in[6];
    const float* W2     = (const float*)d_in[7];
    const float* a_src2 = (const float*)d_in[8];
    const float* a_dst2 = (const float*)d_in[9];
    const float* b2     = (const float*)d_in[10];
    const float* Wm1    = (const float*)d_in[11];
    const float* bm1    = (const float*)d_in[12];
    const float* Wm2    = (const float*)d_in[13];
    const float* bm2    = (const float*)d_in[14];
    const float* Wp1    = (const float*)d_in[15];
    const float* bp1    = (const float*)d_in[16];
    const float* Wp2    = (const float*)d_in[17];
    const float* bp2    = (const float*)d_in[18];
    float* out = (float*)d_out;

    float *gh, *gP;
    __nv_bfloat16 *xh, *xl, *y1h, *y1l, *y2h, *y2l, *w1h, *w1l, *w2h, *w2l, *wch, *wcl;
    cudaGetSymbolAddress((void**)&gh,  g_h);
    cudaGetSymbolAddress((void**)&gP,  g_P);
    cudaGetSymbolAddress((void**)&xh,  g_xh);  cudaGetSymbolAddress((void**)&xl,  g_xl);
    cudaGetSymbolAddress((void**)&y1h, g_y1h); cudaGetSymbolAddress((void**)&y1l, g_y1l);
    cudaGetSymbolAddress((void**)&y2h, g_y2h); cudaGetSymbolAddress((void**)&y2l, g_y2l);
    cudaGetSymbolAddress((void**)&w1h, g_w1h); cudaGetSymbolAddress((void**)&w1l, g_w1l);
    cudaGetSymbolAddress((void**)&w2h, g_w2h); cudaGetSymbolAddress((void**)&w2l, g_w2l);
    cudaGetSymbolAddress((void**)&wch, g_wch); cudaGetSymbolAddress((void**)&wcl, g_wcl);

    cudaFuncSetAttribute(gemm_bf16, cudaFuncAttributeMaxDynamicSharedMemorySize, GEMM_SMEM);

    const int MT = (NN + 127) / 128;   // 391

    // prep first (keeps gemm_bf16 at the profiled launch slot)
    fsplit  <<<(NN * DIN + 255) / 256, 256>>>(x, xh, xl, NN * DIN);
    wprep   <<<(DIN * F + 255) / 256, 256>>>(W1, w1h, w1l, DIN, F);
    wprep   <<<(F * F + 255) / 256, 256>>>(W2, w2h, w2l, F, F);

    // layer-1 GEMM
    gemm_bf16<<<dim3(MT, 4), 256, GEMM_SMEM>>>(xh, xl, w1h, w1l, gh, NN, F, DIN);

    wcatprep<<<(64 * F + 255) / 256, 256>>>(Wp1);

    // CSR
    csr_zero <<<(NN + 255) / 256, 256>>>();
    csr_count<<<(NE + 255) / 256, 256>>>(ei);
    csr_scan <<<1, 1024>>>();
    csr_fill <<<(NE + 255) / 256, 256>>>(ei);

    // layer 1 attention
    alpha_kernel<<<(NN * H * 32 + 255) / 256, 256>>>(a_src1, a_dst1);
    gat_fused<<<(NN * 32 + 255) / 256, 256>>>(b1, y1h, y1l);

    // layer 2
    gemm_bf16<<<dim3(MT, 4), 256, GEMM_SMEM>>>(y1h, y1l, w2h, w2l, gh, NN, F, F);
    alpha_kernel<<<(NN * H * 32 + 255) / 256, 256>>>(a_src2, a_dst2);
    gat_fused<<<(NN * 32 + 255) / 256, 256>>>(b2, y2h, y2l);

    // P projection + tensor edge head
    gemm_bf16<<<dim3(MT, 1), 256, GEMM_SMEM>>>(y2h, y2l, wch, wcl, gP, NN, 64, F);
    mlp_edge<<<NE / 128, 128>>>(ei, ea, Wm1, bm1, Wm2, bm2,
                                Wp1, bp1, Wp2, bp2, out);
}

// round 15
// speedup vs baseline: 3.2048x; 1.1723x over previous
#include <cuda_runtime.h>
#include <cuda_bf16.h>
#include <math.h>
#include <stdint.h>

#define NN 50000
#define NE 400000
#define DIN 128
#define F 256
#define H 8

// ---------------- scratch (device globals; no allocation) ----------------
__device__ float g_h [NN * F];      // h = x @ W for current layer (fp32)
__device__ float g_as[NN * H];
__device__ float g_ad[NN * H];
__device__ float g_P [NN * 64];     // [Prow(32) | Pcol(32)] per node
// split bf16 activations
__device__ __nv_bfloat16 g_xh[NN * DIN], g_xl[NN * DIN];
__device__ __nv_bfloat16 g_y1h[NN * F],  g_y1l[NN * F];
__device__ __nv_bfloat16 g_y2h[NN * F],  g_y2l[NN * F];
// split+transposed weights [N][K] K-major
__device__ __nv_bfloat16 g_w1h[F * DIN], g_w1l[F * DIN];
__device__ __nv_bfloat16 g_w2h[F * F],   g_w2l[F * F];
__device__ __nv_bfloat16 g_wch[64 * F],  g_wcl[64 * F];
// CSR of incoming real edges
__device__ int g_cnt[NN];
__device__ int g_off[NN + 1];
__device__ int g_cur[NN];
__device__ int g_src[NE];

// ---------------- helpers ----------------
__device__ __forceinline__ uint32_t smem_u32(const void* p) {
    uint32_t a;
    asm("{ .reg .u64 t; cvta.to.shared.u64 t, %1; cvt.u32.u64 %0, t; }" : "=r"(a) : "l"(p));
    return a;
}
__device__ __forceinline__ void mma_bf16(float* d, const uint32_t* a, const uint32_t* b) {
    asm volatile(
        "mma.sync.aligned.m16n8k16.row.col.f32.bf16.bf16.f32 "
        "{%0,%1,%2,%3}, {%4,%5,%6,%7}, {%8,%9}, {%0,%1,%2,%3};\n"
        : "+f"(d[0]), "+f"(d[1]), "+f"(d[2]), "+f"(d[3])
        : "r"(a[0]), "r"(a[1]), "r"(a[2]), "r"(a[3]), "r"(b[0]), "r"(b[1]));
}
__device__ __forceinline__ uint32_t packbf(float a, float b) {
    __nv_bfloat162 t = __floats2bfloat162_rn(a, b);
    return *(uint32_t*)&t;
}
__device__ __forceinline__ void split2(float a, float b, uint32_t& hi, uint32_t& lo) {
    float ah = __bfloat162float(__float2bfloat16(a));
    float bh = __bfloat162float(__float2bfloat16(b));
    hi = packbf(ah, bh);
    lo = packbf(a - ah, b - bh);
}
__device__ __forceinline__ void ldsm4(uint32_t* r, uint32_t addr) {
    asm volatile("ldmatrix.sync.aligned.m8n8.x4.shared.b16 {%0,%1,%2,%3}, [%4];"
        : "=r"(r[0]), "=r"(r[1]), "=r"(r[2]), "=r"(r[3]) : "r"(addr));
}
__device__ __forceinline__ void ldsm2(uint32_t* r, uint32_t addr) {
    asm volatile("ldmatrix.sync.aligned.m8n8.x2.shared.b16 {%0,%1}, [%2];"
        : "=r"(r[0]), "=r"(r[1]) : "r"(addr));
}
__device__ __forceinline__ void cpa16(uint32_t dst, const void* src, int sz) {
    asm volatile("cp.async.cg.shared.global [%0], [%1], 16, %2;"
        :: "r"(dst), "l"(src), "r"(sz));
}
#define CPA_COMMIT() asm volatile("cp.async.commit_group;")
#define CPA_WAIT(n)  asm volatile("cp.async.wait_group %0;" :: "n"(n))

// ---------------- split-bf16 tensor GEMM + fused alpha reduction ----------------
// C[M,Ntot] = A[M,K] @ B^T; if ASv != null also computes
// g_as[r*8+head] = sum_c C[r, head*32+c] * ASv[head*32+c] (and same for ADv),
// exploiting warp tile == 32 cols == one head.
#define ASZB (128 * 40 * 2)
#define BSZB (64 * 40 * 2)
#define GEMM_SMEM (4 * ASZB + 4 * BSZB)   // 61440

__global__ void __launch_bounds__(256) gemm_bf16(
        const __nv_bfloat16* __restrict__ Ah, const __nv_bfloat16* __restrict__ Al,
        const __nv_bfloat16* __restrict__ Bh, const __nv_bfloat16* __restrict__ Bl,
        float* __restrict__ C, int M, int Ntot, int K,
        const float* __restrict__ ASv, const float* __restrict__ ADv,
        float* __restrict__ AsOut, float* __restrict__ AdOut) {
    extern __shared__ char dynsmem[];
    const uint32_t sb = smem_u32(dynsmem);
    const uint32_t OAH = 0, OAL = 2 * ASZB, OBH = 4 * ASZB, OBL = 4 * ASZB + 2 * BSZB;

    int tid = threadIdx.x;
    int lane = tid & 31, wid = tid >> 5;
    int wm = wid & 3, wn = wid >> 2;
    int g = lane >> 2, tg = lane & 3;
    int rowBase = blockIdx.x * 128;
    int colBase = blockIdx.y * 64;

    int ar0 = tid >> 2, ac8_0 = (tid & 3) << 3;
    int ar1 = (tid + 256) >> 2, ac8_1 = ac8_0;
    int br = tid >> 2, bc8 = (tid & 3) << 3;

    float acc[2][4][4];
#pragma unroll
    for (int i = 0; i < 2; i++)
#pragma unroll
        for (int j = 0; j < 4; j++)
#pragma unroll
            for (int q = 0; q < 4; q++) acc[i][j][q] = 0.f;

    int nch = K >> 5;

    auto load_stage = [&](int stage, int k0) {
        uint32_t stA = sb + stage * ASZB;
        uint32_t stB = sb + stage * BSZB;
        {
            int gr = rowBase + ar0;
            int sz = (gr < M) ? 16 : 0;
            int grc = (gr < M) ? gr : (M - 1);
            size_t off = (size_t)grc * K + k0 + ac8_0;
            uint32_t d = stA + (ar0 * 40 + ac8_0) * 2;
            cpa16(d + OAH, Ah + off, sz);
            cpa16(d + OAL, Al + off, sz);
        }
        {
            int gr = rowBase + ar1;
            int sz = (gr < M) ? 16 : 0;
            int grc = (gr < M) ? gr : (M - 1);
            size_t off = (size_t)grc * K + k0 + ac8_1;
            uint32_t d = stA + (ar1 * 40 + ac8_1) * 2;
            cpa16(d + OAH, Ah + off, sz);
            cpa16(d + OAL, Al + off, sz);
        }
        {
            size_t off = (size_t)(colBase + br) * K + k0 + bc8;
            uint32_t d = stB + (br * 40 + bc8) * 2;
            cpa16(d + OBH, Bh + off, 16);
            cpa16(d + OBL, Bl + off, 16);
        }
        CPA_COMMIT();
    };

    load_stage(0, 0);

    for (int ch = 0; ch < nch; ch++) {
        if (ch + 1 < nch) {
            load_stage((ch + 1) & 1, (ch + 1) << 5);
            CPA_WAIT(1);
        } else {
            CPA_WAIT(0);
        }
        __syncthreads();

        int stage = ch & 1;
        uint32_t aH = sb + OAH + stage * ASZB;
        uint32_t aL = sb + OAL + stage * ASZB;
        uint32_t bH = sb + OBH + stage * BSZB;
        uint32_t bL = sb + OBL + stage * BSZB;

        int l16 = lane & 15;
        int arow = (lane & 15), ak8 = (lane >> 4) << 3;
        int brow = l16 & 7, bk8 = (l16 >> 3) << 3;

#pragma unroll
        for (int ks = 0; ks < 2; ks++) {
            uint32_t ah[2][4], al[2][4], bh[4][2], bl[4][2];
#pragma unroll
            for (int i = 0; i < 2; i++) {
                int r = wm * 32 + i * 16 + arow;
                uint32_t o = (uint32_t)(r * 40 + ks * 16 + ak8) * 2;
                ldsm4(ah[i], aH + o);
                ldsm4(al[i], aL + o);
            }
#pragma unroll
            for (int j = 0; j < 4; j++) {
                int n = wn * 32 + j * 8 + brow;
                uint32_t o = (uint32_t)(n * 40 + ks * 16 + bk8) * 2;
                ldsm2(bh[j], bH + o);
                ldsm2(bl[j], bL + o);
            }
#pragma unroll
            for (int i = 0; i < 2; i++)
#pragma unroll
                for (int j = 0; j < 4; j++) {
                    mma_bf16(acc[i][j], ah[i], bl[j]);
                    mma_bf16(acc[i][j], al[i], bh[j]);
                    mma_bf16(acc[i][j], ah[i], bh[j]);
                }
        }
        __syncthreads();
    }

    // C store
#pragma unroll
    for (int i = 0; i < 2; i++) {
        int r = rowBase + wm * 32 + i * 16 + g;
#pragma unroll
        for (int j = 0; j < 4; j++) {
            int c = colBase + wn * 32 + j * 8 + 2 * tg;
            if (r < M)
                *(float2*)&C[(size_t)r * Ntot + c] = make_float2(acc[i][j][0], acc[i][j][1]);
            if (r + 8 < M)
                *(float2*)&C[(size_t)(r + 8) * Ntot + c] = make_float2(acc[i][j][2], acc[i][j][3]);
        }
    }

    // fused alpha: warp tile = one head
    if (ASv) {
        float asv[8], adw[8];
#pragma unroll
        for (int j = 0; j < 4; j++) {
            int c = colBase + wn * 32 + j * 8 + 2 * tg;
            asv[2 * j]     = ASv[c];
            asv[2 * j + 1] = ASv[c + 1];
            adw[2 * j]     = ADv[c];
            adw[2 * j + 1] = ADv[c + 1];
        }
        int head = (colBase >> 5) + wn;
#pragma unroll
        for (int i = 0; i < 2; i++) {
            float s0 = 0.f, s1 = 0.f, d0 = 0.f, d1 = 0.f;
#pragma unroll
            for (int j = 0; j < 4; j++) {
                s0 += acc[i][j][0] * asv[2 * j] + acc[i][j][1] * asv[2 * j + 1];
                s1 += acc[i][j][2] * asv[2 * j] + acc[i][j][3] * asv[2 * j + 1];
                d0 += acc[i][j][0] * adw[2 * j] + acc[i][j][1] * adw[2 * j + 1];
                d1 += acc[i][j][2] * adw[2 * j] + acc[i][j][3] * adw[2 * j + 1];
            }
#pragma unroll
            for (int o = 1; o <= 2; o <<= 1) {
                s0 += __shfl_xor_sync(0xFFFFFFFFu, s0, o);
                s1 += __shfl_xor_sync(0xFFFFFFFFu, s1, o);
                d0 += __shfl_xor_sync(0xFFFFFFFFu, d0, o);
                d1 += __shfl_xor_sync(0xFFFFFFFFu, d1, o);
            }
            if (tg == 0) {
                int r = rowBase + wm * 32 + i * 16 + g;
                if (r < M)     { AsOut[r * 8 + head] = s0;       AdOut[r * 8 + head] = d0; }
                if (r + 8 < M) { AsOut[(r + 8) * 8 + head] = s1; AdOut[(r + 8) * 8 + head] = d1; }
            }
        }
    }
}

// ---------------- prep kernels ----------------
__global__ void fsplit(const float* __restrict__ s, __nv_bfloat16* __restrict__ h,
                       __nv_bfloat16* __restrict__ l, int n) {
    int i = blockIdx.x * blockDim.x + threadIdx.x;
    if (i >= n) return;
    float v = s[i];
    __nv_bfloat16 hi = __float2bfloat16(v);
    h[i] = hi;
    l[i] = __float2bfloat16(v - __bfloat162float(hi));
}
__global__ void wprep(const float* __restrict__ W, __nv_bfloat16* __restrict__ th,
                      __nv_bfloat16* __restrict__ tl, int K, int N) {
    int i = blockIdx.x * blockDim.x + threadIdx.x;
    if (i >= K * N) return;
    int k = i / N, n = i % N;
    float v = W[i];
    __nv_bfloat16 hi = __float2bfloat16(v);
    th[n * K + k] = hi;
    tl[n * K + k] = __float2bfloat16(v - __bfloat162float(hi));
}
__global__ void wcatprep(const float* __restrict__ Wp1) {
    int i = blockIdx.x * blockDim.x + threadIdx.x;
    if (i >= 64 * 256) return;
    int j = i / 256, k = i % 256;
    float v = (j < 32) ? Wp1[k * 32 + j] : Wp1[(256 + k) * 32 + (j - 32)];
    __nv_bfloat16 hi = __float2bfloat16(v);
    g_wch[i] = hi;
    g_wcl[i] = __float2bfloat16(v - __bfloat162float(hi));
}

// ---------------- CSR build ----------------
__global__ void csr_zero() {
    int i = blockIdx.x * blockDim.x + threadIdx.x;
    if (i < NN) g_cnt[i] = 0;
}
__global__ void csr_count(const int* __restrict__ ei) {
    int e = blockIdx.x * blockDim.x + threadIdx.x;
    if (e < NE) atomicAdd(&g_cnt[ei[NE + e]], 1);
}
__global__ void csr_scan() {
    __shared__ int wsum[32];
    __shared__ int carry_s;
    int t = threadIdx.x, lane = t & 31, wid = t >> 5;
    if (t == 0) carry_s = 0;
    __syncthreads();
    for (int base = 0; base < NN; base += 1024) {
        int i = base + t;
        int v = (i < NN) ? g_cnt[i] : 0;
        int x = v;
#pragma unroll
        for (int o = 1; o < 32; o <<= 1) {
            int y = __shfl_up_sync(0xFFFFFFFFu, x, o);
            if (lane >= o) x += y;
        }
        if (lane == 31) wsum[wid] = x;
        __syncthreads();
        if (wid == 0) {
            int s = wsum[lane];
#pragma unroll
            for (int o = 1; o < 32; o <<= 1) {
                int y = __shfl_up_sync(0xFFFFFFFFu, s, o);
                if (lane >= o) s += y;
            }
            wsum[lane] = s;
        }
        __syncthreads();
        int inc = x + (wid > 0 ? wsum[wid - 1] : 0);
        int exc = carry_s + inc - v;
        if (i < NN) { g_off[i] = exc; g_cur[i] = exc; }
        __syncthreads();
        if (t == 1023) carry_s += wsum[31];
        __syncthreads();
    }
    if (t == 0) g_off[NN] = NE;
}
__global__ void csr_fill(const int* __restrict__ ei) {
    int e = blockIdx.x * blockDim.x + threadIdx.x;
    if (e >= NE) return;
    int d = ei[NE + e];
    int pos = atomicAdd(&g_cur[d], 1);
    g_src[pos] = ei[e];
}

// ---------------- fused softmax-attention aggregation: warp per dst ----------------
__global__ void gat_fused(const float* __restrict__ b,
                          __nv_bfloat16* __restrict__ oh, __nv_bfloat16* __restrict__ ol) {
    int w = (blockIdx.x * blockDim.x + threadIdx.x) >> 5;
    int lane = threadIdx.x & 31;
    if (w >= NN) return;
    const int d = w;

    float4 t0 = *(const float4*)&g_ad[d * 8];
    float4 t1 = *(const float4*)&g_ad[d * 8 + 4];
    float adv[8] = {t0.x, t0.y, t0.z, t0.w, t1.x, t1.y, t1.z, t1.w};
    float4 s0 = *(const float4*)&g_as[d * 8];
    float4 s1 = *(const float4*)&g_as[d * 8 + 4];
    float eslf[8];
    {
        float slf[8] = {s0.x, s0.y, s0.z, s0.w, s1.x, s1.y, s1.z, s1.w};
#pragma unroll
        for (int h = 0; h < 8; h++) {
            float e = slf[h] + adv[h];
            eslf[h] = (e > 0.f) ? e : 0.2f * e;
        }
    }

    int beg = g_off[d], end = g_off[d + 1];
    int cnt = end - beg;

    float num[8], den[8];

    if (cnt <= 32) {
        int sown = 0;
        float e8[8];
        if (lane < cnt) {
            sown = g_src[beg + lane];
            float4 a0 = *(const float4*)&g_as[sown * 8];
            float4 a1 = *(const float4*)&g_as[sown * 8 + 4];
            float av[8] = {a0.x, a0.y, a0.z, a0.w, a1.x, a1.y, a1.z, a1.w};
#pragma unroll
            for (int h = 0; h < 8; h++) {
                float e = av[h] + adv[h];
                e8[h] = (e > 0.f) ? e : 0.2f * e;
            }
        } else {
#pragma unroll
            for (int h = 0; h < 8; h++) e8[h] = -1e30f;
        }
        float mx[8];
#pragma unroll
        for (int h = 0; h < 8; h++) {
            float m = e8[h];
#pragma unroll
            for (int o = 16; o; o >>= 1)
                m = fmaxf(m, __shfl_xor_sync(0xFFFFFFFFu, m, o));
            mx[h] = fmaxf(m, eslf[h]);
        }
        float ex8[8];
#pragma unroll
        for (int h = 0; h < 8; h++)
            ex8[h] = (lane < cnt) ? expf(e8[h] - mx[h]) : 0.f;
#pragma unroll
        for (int h = 0; h < 8; h++) {
            float exs = expf(eslf[h] - mx[h]);
            den[h] = exs;
            num[h] = exs * g_h[d * F + h * 32 + lane];
        }
        int j = 0;
        for (; j + 1 < cnt; j += 2) {
            int sA = __shfl_sync(0xFFFFFFFFu, sown, j);
            int sB = __shfl_sync(0xFFFFFFFFu, sown, j + 1);
            const float* rA = &g_h[(size_t)sA * F];
            const float* rB = &g_h[(size_t)sB * F];
            float vA[8], vB[8];
#pragma unroll
            for (int h = 0; h < 8; h++) vA[h] = rA[h * 32 + lane];
#pragma unroll
            for (int h = 0; h < 8; h++) vB[h] = rB[h * 32 + lane];
#pragma unroll
            for (int h = 0; h < 8; h++) {
                float cA = __shfl_sync(0xFFFFFFFFu, ex8[h], j);
                float cB = __shfl_sync(0xFFFFFFFFu, ex8[h], j + 1);
                den[h] += cA + cB;
                num[h] += cA * vA[h] + cB * vB[h];
            }
        }
        if (j < cnt) {
            int sA = __shfl_sync(0xFFFFFFFFu, sown, j);
            const float* rA = &g_h[(size_t)sA * F];
#pragma unroll
            for (int h = 0; h < 8; h++) {
                float cA = __shfl_sync(0xFFFFFFFFu, ex8[h], j);
                den[h] += cA;
                num[h] += cA * rA[h * 32 + lane];
            }
        }
    } else {
        float mx[8];
#pragma unroll
        for (int h = 0; h < 8; h++) mx[h] = eslf[h];
        for (int i = beg + lane; i < end; i += 32) {
            int s = g_src[i];
            float4 a0 = *(const float4*)&g_as[s * 8];
            float4 a1 = *(const float4*)&g_as[s * 8 + 4];
            float av[8] = {a0.x, a0.y, a0.z, a0.w, a1.x, a1.y, a1.z, a1.w};
#pragma unroll
            for (int h = 0; h < 8; h++) {
                float e = av[h] + adv[h];
                e = (e > 0.f) ? e : 0.2f * e;
                mx[h] = fmaxf(mx[h], e);
            }
        }
#pragma unroll
        for (int h = 0; h < 8; h++)
#pragma unroll
            for (int o = 16; o; o >>= 1)
                mx[h] = fmaxf(mx[h], __shfl_xor_sync(0xFFFFFFFFu, mx[h], o));

#pragma unroll
        for (int h = 0; h < 8; h++) {
            float exs = expf(eslf[h] - mx[h]);
            den[h] = exs;
            num[h] = exs * g_h[d * F + h * 32 + lane];
        }
        for (int base = beg; base < end; base += 32) {
            int m = end - base;
            if (m > 32) m = 32;
            int sown = 0;
            float ex8[8];
            if (lane < m) {
                sown = g_src[base + lane];
                float4 a0 = *(const float4*)&g_as[sown * 8];
                float4 a1 = *(const float4*)&g_as[sown * 8 + 4];
                float av[8] = {a0.x, a0.y, a0.z, a0.w, a1.x, a1.y, a1.z, a1.w};
#pragma unroll
                for (int h = 0; h < 8; h++) {
                    float e = av[h] + adv[h];
                    e = (e > 0.f) ? e : 0.2f * e;
                    ex8[h] = expf(e - mx[h]);
                }
            } else {
#pragma unroll
                for (int h = 0; h < 8; h++) ex8[h] = 0.f;
            }
            int j = 0;
            for (; j + 1 < m; j += 2) {
                int sA = __shfl_sync(0xFFFFFFFFu, sown, j);
                int sB = __shfl_sync(0xFFFFFFFFu, sown, j + 1);
                const float* rA = &g_h[(size_t)sA * F];
                const float* rB = &g_h[(size_t)sB * F];
                float vA[8], vB[8];
#pragma unroll
                for (int h = 0; h < 8; h++) vA[h] = rA[h * 32 + lane];
#pragma unroll
                for (int h = 0; h < 8; h++) vB[h] = rB[h * 32 + lane];
#pragma unroll
                for (int h = 0; h < 8; h++) {
                    float cA = __shfl_sync(0xFFFFFFFFu, ex8[h], j);
                    float cB = __shfl_sync(0xFFFFFFFFu, ex8[h], j + 1);
                    den[h] += cA + cB;
                    num[h] += cA * vA[h] + cB * vB[h];
                }
            }
            if (j < m) {
                int sA = __shfl_sync(0xFFFFFFFFu, sown, j);
                const float* rA = &g_h[(size_t)sA * F];
#pragma unroll
                for (int h = 0; h < 8; h++) {
                    float cA = __shfl_sync(0xFFFFFFFFu, ex8[h], j);
                    den[h] += cA;
                    num[h] += cA * rA[h * 32 + lane];
                }
            }
        }
    }

#pragma unroll
    for (int h = 0; h < 8; h++) {
        float v = num[h] / den[h] + b[h * 32 + lane];
        v = (v > 0.f) ? v : 0.f;
        __nv_bfloat16 hi = __float2bfloat16(v);
        oh[d * F + h * 32 + lane] = hi;
        ol[d * F + h * 32 + lane] = __float2bfloat16(v - __bfloat162float(hi));
    }
}

// ---------------- tensor-core edge head: 128 edges per block, 4 warps ----------------
__global__ void __launch_bounds__(128) mlp_edge(
        const int* __restrict__ ei, const float* __restrict__ ea,
        const float* __restrict__ Wm1, const float* __restrict__ bm1,
        const float* __restrict__ Wm2, const float* __restrict__ bm2,
        const float* __restrict__ Wp1, const float* __restrict__ bp1,
        const float* __restrict__ Wp2, const float* __restrict__ bp2,
        float* __restrict__ out) {
    __shared__ union {
        uint32_t ea32[2][128 * 20];
        float    q[128 * 33];
    } uS;
    __shared__ uint32_t sW[6][32 * 20];
    __shared__ float sb1[32], sb2[32], sbp1[32], sWp2[32];

    int tid = threadIdx.x;
    int lane = tid & 31, wid = tid >> 5;
    int g = lane >> 2, tg = lane & 3;
    int ebase = blockIdx.x * 128;

    for (int t = tid; t < 1024; t += 128) {
        int i = t >> 5, o = t & 31;
        float v1 = Wm1[i * 32 + o];
        float v2 = Wm2[i * 32 + o];
        float v3 = Wp1[(512 + i) * 32 + o];
        __nv_bfloat16* w0 = (__nv_bfloat16*)sW[0];
        __nv_bfloat16* w1 = (__nv_bfloat16*)sW[1];
        __nv_bfloat16* w2 = (__nv_bfloat16*)sW[2];
        __nv_bfloat16* w3 = (__nv_bfloat16*)sW[3];
        __nv_bfloat16* w4 = (__nv_bfloat16*)sW[4];
        __nv_bfloat16* w5 = (__nv_bfloat16*)sW[5];
        int idx = o * 40 + i;
        __nv_bfloat16 h1 = __float2bfloat16(v1);
        __nv_bfloat16 h2 = __float2bfloat16(v2);
        __nv_bfloat16 h3 = __float2bfloat16(v3);
        w0[idx] = h1; w1[idx] = __float2bfloat16(v1 - __bfloat162float(h1));
        w2[idx] = h2; w3[idx] = __float2bfloat16(v2 - __bfloat162float(h2));
        w4[idx] = h3; w5[idx] = __float2bfloat16(v3 - __bfloat162float(h3));
    }
    if (tid < 32) {
        sb1[tid] = bm1[tid];
        sb2[tid] = bm2[tid];
        sbp1[tid] = bp1[tid];
        sWp2[tid] = Wp2[tid];
    }

    {
        int e = ebase + tid;
        const float4* src = (const float4*)&ea[(size_t)e * 32];
#pragma unroll
        for (int q4 = 0; q4 < 8; q4++) {
            float4 v = src[q4];
            uint32_t h0, l0, h1, l1;
            split2(v.x, v.y, h0, l0);
            split2(v.z, v.w, h1, l1);
            uS.ea32[0][tid * 20 + q4 * 2]     = h0;
            uS.ea32[0][tid * 20 + q4 * 2 + 1] = h1;
            uS.ea32[1][tid * 20 + q4 * 2]     = l0;
            uS.ea32[1][tid * 20 + q4 * 2 + 1] = l1;
        }
    }
    __syncthreads();

    float acc[2][4][4];
#pragma unroll
    for (int i = 0; i < 2; i++)
#pragma unroll
        for (int j = 0; j < 4; j++)
#pragma unroll
            for (int q = 0; q < 4; q++) acc[i][j][q] = 0.f;

    {
        uint32_t bh[4][2][2], bl[4][2][2];
#pragma unroll
        for (int j = 0; j < 4; j++)
#pragma unroll
            for (int ks = 0; ks < 2; ks++) {
                int n = j * 8 + g, ko = ks * 8;
                bh[j][ks][0] = sW[0][n * 20 + ko + tg];
                bh[j][ks][1] = sW[0][n * 20 + ko + 4 + tg];
                bl[j][ks][0] = sW[1][n * 20 + ko + tg];
                bl[j][ks][1] = sW[1][n * 20 + ko + 4 + tg];
            }
#pragma unroll
        for (int ks = 0; ks < 2; ks++) {
            int ko = ks * 8;
            uint32_t ah[2][4], al[2][4];
#pragma unroll
            for (int i = 0; i < 2; i++) {
                int r = wid * 32 + i * 16 + g;
                ah[i][0] = uS.ea32[0][r * 20 + ko + tg];
                ah[i][1] = uS.ea32[0][(r + 8) * 20 + ko + tg];
                ah[i][2] = uS.ea32[0][r * 20 + ko + 4 + tg];
                ah[i][3] = uS.ea32[0][(r + 8) * 20 + ko + 4 + tg];
                al[i][0] = uS.ea32[1][r * 20 + ko + tg];
                al[i][1] = uS.ea32[1][(r + 8) * 20 + ko + tg];
                al[i][2] = uS.ea32[1][r * 20 + ko + 4 + tg];
                al[i][3] = uS.ea32[1][(r + 8) * 20 + ko + 4 + tg];
            }
#pragma unroll
            for (int i = 0; i < 2; i++)
#pragma unroll
                for (int j = 0; j < 4; j++) {
                    mma_bf16(acc[i][j], ah[i], bl[j][ks]);
                    mma_bf16(acc[i][j], al[i], bh[j][ks]);
                    mma_bf16(acc[i][j], ah[i], bh[j][ks]);
                }
        }
    }

#define STAGE(WH, WL, BIAS)                                                       \
    {                                                                             \
        uint32_t ah2[2][2][4], al2[2][2][4];                                      \
        _Pragma("unroll")                                                         \
        for (int i = 0; i < 2; i++)                                               \
            _Pragma("unroll")                                                     \
            for (int ks = 0; ks < 2; ks++) {                                      \
                int j0 = ks * 2, j1 = ks * 2 + 1;                                 \
                float b0 = (BIAS)[j0 * 8 + 2 * tg], b0b = (BIAS)[j0 * 8 + 2 * tg + 1]; \
                float b1 = (BIAS)[j1 * 8 + 2 * tg], b1b = (BIAS)[j1 * 8 + 2 * tg + 1]; \
                float v00 = fmaxf(acc[i][j0][0] + b0, 0.f);                       \
                float v01 = fmaxf(acc[i][j0][1] + b0b, 0.f);                      \
                float v02 = fmaxf(acc[i][j0][2] + b0, 0.f);                       \
                float v03 = fmaxf(acc[i][j0][3] + b0b, 0.f);                      \
                float v10 = fmaxf(acc[i][j1][0] + b1, 0.f);                       \
                float v11 = fmaxf(acc[i][j1][1] + b1b, 0.f);                      \
                float v12 = fmaxf(acc[i][j1][2] + b1, 0.f);                       \
                float v13 = fmaxf(acc[i][j1][3] + b1b, 0.f);                      \
                split2(v00, v01, ah2[i][ks][0], al2[i][ks][0]);                   \
                split2(v02, v03, ah2[i][ks][1], al2[i][ks][1]);                   \
                split2(v10, v11, ah2[i][ks][2], al2[i][ks][2]);                   \
                split2(v12, v13, ah2[i][ks][3], al2[i][ks][3]);                   \
            }                                                                     \
        _Pragma("unroll")                                                         \
        for (int i = 0; i < 2; i++)                                               \
            _Pragma("unroll")                                                     \
            for (int j = 0; j < 4; j++)                                           \
                _Pragma("unroll")                                                 \
                for (int q = 0; q < 4; q++) acc[i][j][q] = 0.f;                   \
        _Pragma("unroll")                                                         \
        for (int ks = 0; ks < 2; ks++) {                                          \
            int ko = ks * 8;                                                      \
            _Pragma("unroll")                                                     \
            for (int j = 0; j < 4; j++) {                                         \
                int n = j * 8 + g;                                                \
                uint32_t wbh[2], wbl[2];                                          \
                wbh[0] = (WH)[n * 20 + ko + tg];                                  \
                wbh[1] = (WH)[n * 20 + ko + 4 + tg];                              \
                wbl[0] = (WL)[n * 20 + ko + tg];                                  \
                wbl[1] = (WL)[n * 20 + ko + 4 + tg];                              \
                _Pragma("unroll")                                                 \
                for (int i = 0; i < 2; i++) {                                     \
                    mma_bf16(acc[i][j], ah2[i][ks], wbl);                         \
                    mma_bf16(acc[i][j], al2[i][ks], wbh);                         \
                    mma_bf16(acc[i][j], ah2[i][ks], wbh);                         \
                }                                                                 \
            }                                                                     \
        }                                                                         \
    }

    STAGE(sW[2], sW[3], sb1)
    STAGE(sW[4], sW[5], sb2)
#undef STAGE

    __syncthreads();
#pragma unroll
    for (int i = 0; i < 2; i++) {
        int r = wid * 32 + i * 16 + g;
#pragma unroll
        for (int j = 0; j < 4; j++) {
            int c = j * 8 + 2 * tg;
            uS.q[r * 33 + c]       = acc[i][j][0];
            uS.q[r * 33 + c + 1]   = acc[i][j][1];
            uS.q[(r + 8) * 33 + c]     = acc[i][j][2];
            uS.q[(r + 8) * 33 + c + 1] = acc[i][j][3];
        }
    }
    __syncwarp();

    // finish: warp iterates its 32 edges with P-gather prefetch; lane = channel
    int rown = ei[ebase + wid * 32 + lane];
    int coln = ei[NE + ebase + wid * 32 + lane];
    float bpv = sbp1[lane], wp2v = sWp2[lane], bp2v = bp2[0];
    int r0 = __shfl_sync(0xFFFFFFFFu, rown, 0);
    int c0 = __shfl_sync(0xFFFFFFFFu, coln, 0);
    float pr = g_P[(size_t)r0 * 64 + lane];
    float pc = g_P[(size_t)c0 * 64 + 32 + lane];
    for (int j = 0; j < 32; j++) {
        float prn = 0.f, pcn = 0.f;
        if (j < 31) {
            int rn = __shfl_sync(0xFFFFFFFFu, rown, j + 1);
            int cn = __shfl_sync(0xFFFFFFFFu, coln, j + 1);
            prn = g_P[(size_t)rn * 64 + lane];
            pcn = g_P[(size_t)cn * 64 + 32 + lane];
        }
        float t = uS.q[(wid * 32 + j) * 33 + lane] + pr + pc + bpv;
        t = fmaxf(t, 0.f);
        float s = t * wp2v;
#pragma unroll
        for (int o = 16; o; o >>= 1) s += __shfl_xor_sync(0xFFFFFFFFu, s, o);
        if (lane == 0) out[ebase + wid * 32 + j] = s + bp2v;
        pr = prn;
        pc = pcn;
    }
}

// ---------------- host driver ----------------
extern "C" void kernel_launch(void* const* d_in, const int* in_sizes, int n_in,
                              void* d_out, int out_size) {
    const float* x      = (const float*)d_in[0];
    const int*   ei     = (const int*)  d_in[1];
    const float* ea     = (const float*)d_in[2];
    const float* W1     = (const float*)d_in[3];
    const float* a_src1 = (const float*)d_in[4];
    const float* a_dst1 = (const float*)d_in[5];
    const float* b1     = (const float*)d_in[6];
    const float* W2     = (const float*)d_in[7];
    const float* a_src2 = (const float*)d_in[8];
    const float* a_dst2 = (const float*)d_in[9];
    const float* b2     = (const float*)d_in[10];
    const float* Wm1    = (const float*)d_in[11];
    const float* bm1    = (const float*)d_in[12];
    const float* Wm2    = (const float*)d_in[13];
    const float* bm2    = (const float*)d_in[14];
    const float* Wp1    = (const float*)d_in[15];
    const float* bp1    = (const float*)d_in[16];
    const float* Wp2    = (const float*)d_in[17];
    const float* bp2    = (const float*)d_in[18];
    float* out = (float*)d_out;

    float *gh, *gP, *gas, *gad;
    __nv_bfloat16 *xh, *xl, *y1h, *y1l, *y2h, *y2l, *w1h, *w1l, *w2h, *w2l, *wch, *wcl;
    cudaGetSymbolAddress((void**)&gh,  g_h);
    cudaGetSymbolAddress((void**)&gP,  g_P);
    cudaGetSymbolAddress((void**)&gas, g_as);
    cudaGetSymbolAddress((void**)&gad, g_ad);
    cudaGetSymbolAddress((void**)&xh,  g_xh);  cudaGetSymbolAddress((void**)&xl,  g_xl);
    cudaGetSymbolAddress((void**)&y1h, g_y1h); cudaGetSymbolAddress((void**)&y1l, g_y1l);
    cudaGetSymbolAddress((void**)&y2h, g_y2h); cudaGetSymbolAddress((void**)&y2l, g_y2l);
    cudaGetSymbolAddress((void**)&w1h, g_w1h); cudaGetSymbolAddress((void**)&w1l, g_w1l);
    cudaGetSymbolAddress((void**)&w2h, g_w2h); cudaGetSymbolAddress((void**)&w2l, g_w2l);
    cudaGetSymbolAddress((void**)&wch, g_wch); cudaGetSymbolAddress((void**)&wcl, g_wcl);

    cudaFuncSetAttribute(gemm_bf16, cudaFuncAttributeMaxDynamicSharedMemorySize, GEMM_SMEM);

    const int MT = (NN + 127) / 128;   // 391

    // prep
    fsplit  <<<(NN * DIN + 255) / 256, 256>>>(x, xh, xl, NN * DIN);
    wprep   <<<(DIN * F + 255) / 256, 256>>>(W1, w1h, w1l, DIN, F);
    wprep   <<<(F * F + 255) / 256, 256>>>(W2, w2h, w2l, F, F);

    // layer-1 GEMM (+fused alpha)
    gemm_bf16<<<dim3(MT, 4), 256, GEMM_SMEM>>>(xh, xl, w1h, w1l, gh, NN, F, DIN,
                                               a_src1, a_dst1, gas, gad);

    wcatprep<<<(64 * F + 255) / 256, 256>>>(Wp1);

    // CSR
    csr_zero <<<(NN + 255) / 256, 256>>>();
    csr_count<<<(NE + 255) / 256, 256>>>(ei);
    csr_scan <<<1, 1024>>>();
    csr_fill <<<(NE + 255) / 256, 256>>>(ei);

    // layer 1 attention
    gat_fused<<<(NN * 32 + 255) / 256, 256>>>(b1, y1h, y1l);

    // layer 2 (+fused alpha)
    gemm_bf16<<<dim3(MT, 4), 256, GEMM_SMEM>>>(y1h, y1l, w2h, w2l, gh, NN, F, F,
                                               a_src2, a_dst2, gas, gad);
    gat_fused<<<(NN * 32 + 255) / 256, 256>>>(b2, y2h, y2l);

    // P projection + tensor edge head
    gemm_bf16<<<dim3(MT, 1), 256, GEMM_SMEM>>>(y2h, y2l, wch, wcl, gP, NN, 64, F,
                                               nullptr, nullptr, nullptr, nullptr);
    mlp_edge<<<NE / 128, 128>>>(ei, ea, Wm1, bm1, Wm2, bm2,
                                Wp1, bp1, Wp2, bp2, out);
}